// round 1
// baseline (speedup 1.0000x reference)
#include <cuda_runtime.h>
#include <cuda_bf16.h>
#include <math.h>

// ---------------------------------------------------------------------------
// Problem constants
// ---------------------------------------------------------------------------
#define BATCH 4
#define NV    2048
#define BV    (BATCH * NV)      // 8192
#define NR    5
#define NA    8
#define RA    (NR * NA)         // 40
#define CIN   30
#define CMAX  128
#define TMAX  256
#define KDMAX (RA * CMAX)       // 5120
#define NMAX  (NA * TMAX)       // 2048

// ---------------------------------------------------------------------------
// Scratch (device globals; no runtime allocation allowed)
// ---------------------------------------------------------------------------
__device__ float g_xA[BV * CMAX];          // 8192*128 (also holds normalized input 8192*30)
__device__ float g_xB[BV * TMAX];          // 8192*256
__device__ float g_I [ (long)BV * KDMAX ]; // 8192*5120
__device__ float g_W [ (long)KDMAX * NMAX ]; // 5120*2048
__device__ float g_G [ (long)BV * NMAX ];  // 8192*2048
__device__ float g_part[BATCH * 16 * 256];

// ---------------------------------------------------------------------------
// Normalization constants (Keras adaption stats)
// ---------------------------------------------------------------------------
__constant__ float c_mean[CIN] = {
    -3.7189561e-06f, 0.000286194f, 0.0020740835f, 6.5275993f, -0.0052857199f,
    10.554636f, 0.057773598f, 13.915789f, 0.060970016f, 16.840271f,
    0.0570364f, 19.415283f, 0.044104282f, 21.721455f, 0.11490919f,
    23.64683f, 0.099816084f, 25.365578f, 0.01769533f, 26.861437f,
    0.054662503f, 28.197876f, -0.0024771576f, 29.295244f, 0.039666731f,
    30.319246f, 0.0088442909f, 31.160933f, -0.026727753f, 31.874565f};
__constant__ float c_var[CIN] = {
    3.3091978e-06f, 0.00016750646f, 0.80988622f, 85135.219f, 1.5621265f,
    222580.2f, 8.812871f, 386912.78f, 10.180468f, 566622.44f,
    9.8600769f, 753158.06f, 7.8372045f, 942701.62f, 30.926426f,
    1117233.0f, 25.045353f, 1285543.9f, 6.3646226f, 1441639.1f,
    12.326629f, 1588653.4f, 6.9686499f, 1714707.9f, 10.755516f,
    1836677.8f, 8.416419f, 1940088.8f, 10.344138f, 2029969.6f};

__device__ __forceinline__ float elu1(float x) {
    return x > 0.0f ? x : expm1f(x);
}

// ---------------------------------------------------------------------------
// 1) Input normalization: x0 = (signal - mean) * rsqrt(var)
// ---------------------------------------------------------------------------
__global__ void norm_kernel(const float* __restrict__ sig, float* __restrict__ x0) {
    int i = blockIdx.x * blockDim.x + threadIdx.x;
    if (i < BV * CIN) {
        int c = i % CIN;
        x0[i] = (sig[i] - c_mean[c]) * rsqrtf(c_var[c]);
    }
}

// ---------------------------------------------------------------------------
// 2) Barycentric gather + interpolation:
//    I[bv, ra*C + c] = sum_j w[bv,ra,j] * x[b, idx[bv,ra,j], c]
//    One block per (bv, ra); threads over channel c.
// ---------------------------------------------------------------------------
__global__ void interp_kernel(const float* __restrict__ x, int C,
                              const int* __restrict__ bc_idx,
                              const float* __restrict__ bc_w,
                              float* __restrict__ I) {
    int blk = blockIdx.x;               // bv*RA + ra
    int bv  = blk / RA;
    int ra  = blk % RA;
    int b   = bv >> 11;                 // / NV
    const int*   idx = bc_idx + (long)blk * 3;
    const float* w   = bc_w   + (long)blk * 3;
    int i0 = idx[0], i1 = idx[1], i2 = idx[2];
    float w0 = w[0], w1 = w[1], w2 = w[2];
    int c = threadIdx.x;
    if (c < C) {
        long base = (long)b * NV * C;
        float acc = w0 * x[base + (long)i0 * C + c]
                  + w1 * x[base + (long)i1 * C + c]
                  + w2 * x[base + (long)i2 * C + c];
        I[(long)bv * (RA * C) + ra * C + c] = acc;
    }
}

// ---------------------------------------------------------------------------
// 3) Expand rotated kernel stack into GEMM B matrix:
//    W[(r*NA+a)*C + c, o*T + t] = K[r, (a-o) mod NA, t, c]
// ---------------------------------------------------------------------------
__global__ void rot_kernel(const float* __restrict__ K, int T, int C,
                           float* __restrict__ W) {
    long i = (long)blockIdx.x * blockDim.x + threadIdx.x;
    int  N = NA * T;
    long total = (long)RA * C * N;
    if (i >= total) return;
    long row = i / N;
    int  col = (int)(i - row * N);
    int c  = (int)(row % C);
    int ra = (int)(row / C);
    int a  = ra % NA;
    int r  = ra / NA;
    int t  = col % T;
    int o  = col / T;
    int as = (a - o + NA) & (NA - 1);
    W[i] = K[(((long)r * NA + as) * T + t) * C + c];
}

// ---------------------------------------------------------------------------
// 4) SGEMM: C[M,N] = A[M,Kd] @ B[Kd,N], all row-major.
//    128x128 block tile, BK=8, 8x8 per thread, 256 threads.
//    Requires M%128==0, N%128==0, Kd%8==0 (true for all layers).
// ---------------------------------------------------------------------------
#define GBM 128
#define GBN 128
#define GBK 8
#define GTM 8
#define GTN 8

__global__ __launch_bounds__(256)
void sgemm(const float* __restrict__ A, const float* __restrict__ B,
           float* __restrict__ C, int M, int N, int Kd) {
    __shared__ float As[GBK][GBM];
    __shared__ float Bs[GBK][GBN];
    int tid = threadIdx.x;
    int bx = blockIdx.x;          // N tile
    int by = blockIdx.y;          // M tile
    int tx = tid & 15;
    int ty = tid >> 4;

    const float* Ab = A + (long)by * GBM * Kd;
    const float* Bb = B + (long)bx * GBN;

    int arow = tid >> 1, acol = (tid & 1) * 4;
    int brow = tid >> 5, bcol = (tid & 31) * 4;

    float acc[GTM][GTN];
#pragma unroll
    for (int i = 0; i < GTM; i++)
#pragma unroll
        for (int j = 0; j < GTN; j++) acc[i][j] = 0.0f;

    for (int k0 = 0; k0 < Kd; k0 += GBK) {
        float4 av = *(const float4*)(Ab + (long)arow * Kd + k0 + acol);
        float4 bv = *(const float4*)(Bb + (long)(k0 + brow) * N + bcol);
        As[acol + 0][arow] = av.x;
        As[acol + 1][arow] = av.y;
        As[acol + 2][arow] = av.z;
        As[acol + 3][arow] = av.w;
        *(float4*)(&Bs[brow][bcol]) = bv;
        __syncthreads();
#pragma unroll
        for (int k = 0; k < GBK; k++) {
            float af[GTM], bf[GTN];
#pragma unroll
            for (int i = 0; i < GTM; i++) af[i] = As[k][ty * GTM + i];
#pragma unroll
            for (int j = 0; j < GTN; j++) bf[j] = Bs[k][tx * GTN + j];
#pragma unroll
            for (int i = 0; i < GTM; i++)
#pragma unroll
                for (int j = 0; j < GTN; j++)
                    acc[i][j] += af[i] * bf[j];
        }
        __syncthreads();
    }

    float* Cb = C + (long)(by * GBM + ty * GTM) * N + bx * GBN + tx * GTN;
#pragma unroll
    for (int i = 0; i < GTM; i++)
#pragma unroll
        for (int j = 0; j < GTN; j++)
            Cb[(long)i * N + j] = acc[i][j];
}

// ---------------------------------------------------------------------------
// 5) Epilogue: bias + ELU, angular max pooling (argmax of L2 norm over the 8
//    rotations), then inference BN. One block per vertex, blockDim = T.
// ---------------------------------------------------------------------------
__global__ void amp_kernel(const float* __restrict__ gout, int T,
                           const float* __restrict__ bias,
                           const float* __restrict__ gamma,
                           const float* __restrict__ beta,
                           float* __restrict__ xnext) {
    __shared__ float s[NA * TMAX];
    int bv = blockIdx.x;
    int t  = threadIdx.x;
    int bd = blockDim.x;   // == T
    const float* row = gout + (long)bv * NA * T;
    float y[NA];
#pragma unroll
    for (int o = 0; o < NA; o++) {
        float v = row[o * T + t] + bias[t];
        v = elu1(v);
        y[o] = v;
        s[o * bd + t] = v * v;
    }
    __syncthreads();
    for (int stride = bd >> 1; stride > 0; stride >>= 1) {
        if (t < stride) {
#pragma unroll
            for (int o = 0; o < NA; o++)
                s[o * bd + t] += s[o * bd + t + stride];
        }
        __syncthreads();
    }
    int best = 0;
    float bn = s[0];
#pragma unroll
    for (int o = 1; o < NA; o++) {
        float v = s[o * bd];
        if (v > bn) { bn = v; best = o; }
    }
    float scale = rsqrtf(1.0f + 1e-3f);
    xnext[(long)bv * T + t] = gamma[t] * y[best] * scale + beta[t];
}

// ---------------------------------------------------------------------------
// 6) Global max pool over vertices (two-stage)
// ---------------------------------------------------------------------------
__global__ void gmax_partial(const float* __restrict__ x, float* __restrict__ part) {
    int b = blockIdx.x, ch = blockIdx.y, t = threadIdx.x;
    float m = -3.4e38f;
    int v0 = ch * (NV / 16);
    for (int v = v0; v < v0 + NV / 16; v++)
        m = fmaxf(m, x[((long)(b * NV + v)) * 256 + t]);
    part[(b * 16 + ch) * 256 + t] = m;
}

// ---------------------------------------------------------------------------
// 7) MLP head: 256 -> 512 (elu) -> 256 (elu) -> 40. One block per batch.
// ---------------------------------------------------------------------------
__global__ void mlp_kernel(const float* __restrict__ part,
                           const float* __restrict__ w1, const float* __restrict__ c1,
                           const float* __restrict__ w2, const float* __restrict__ c2,
                           const float* __restrict__ w3, const float* __restrict__ c3,
                           float* __restrict__ out) {
    int b = blockIdx.x, tid = threadIdx.x;  // 512 threads
    __shared__ float h0[256], h1[512], h2[256];
    if (tid < 256) {
        float m = -3.4e38f;
        for (int ch = 0; ch < 16; ch++)
            m = fmaxf(m, part[(b * 16 + ch) * 256 + tid]);
        h0[tid] = m;
    }
    __syncthreads();
    {
        float acc = c1[tid];
        for (int k = 0; k < 256; k++) acc += h0[k] * w1[k * 512 + tid];
        h1[tid] = elu1(acc);
    }
    __syncthreads();
    if (tid < 256) {
        float acc = c2[tid];
        for (int k = 0; k < 512; k++) acc += h1[k] * w2[k * 256 + tid];
        h2[tid] = elu1(acc);
    }
    __syncthreads();
    if (tid < 40) {
        float acc = c3[tid];
        for (int k = 0; k < 256; k++) acc += h2[k] * w3[k * 40 + tid];
        out[b * 40 + tid] = acc;
    }
}

// ---------------------------------------------------------------------------
// Launch
// ---------------------------------------------------------------------------
extern "C" void kernel_launch(void* const* d_in, const int* in_sizes, int n_in,
                              void* d_out, int out_size) {
    const float* signal = (const float*)d_in[0];
    const int*   bc_idx = (const int*)  d_in[1];
    const float* bc_w   = (const float*)d_in[2];
    const float* Kw[3]  = {(const float*)d_in[3],  (const float*)d_in[7],  (const float*)d_in[11]};
    const float* Bw[3]  = {(const float*)d_in[4],  (const float*)d_in[8],  (const float*)d_in[12]};
    const float* Gw[3]  = {(const float*)d_in[5],  (const float*)d_in[9],  (const float*)d_in[13]};
    const float* Ew[3]  = {(const float*)d_in[6],  (const float*)d_in[10], (const float*)d_in[14]};
    const float* w1 = (const float*)d_in[15]; const float* c1 = (const float*)d_in[16];
    const float* w2 = (const float*)d_in[17]; const float* c2 = (const float*)d_in[18];
    const float* w3 = (const float*)d_in[19]; const float* c3 = (const float*)d_in[20];
    float* out = (float*)d_out;

    float *xA, *xB, *Ibuf, *Wbuf, *Gbuf, *Part;
    cudaGetSymbolAddress((void**)&xA,   g_xA);
    cudaGetSymbolAddress((void**)&xB,   g_xB);
    cudaGetSymbolAddress((void**)&Ibuf, g_I);
    cudaGetSymbolAddress((void**)&Wbuf, g_W);
    cudaGetSymbolAddress((void**)&Gbuf, g_G);
    cudaGetSymbolAddress((void**)&Part, g_part);

    norm_kernel<<<(BV * CIN + 255) / 256, 256>>>(signal, xA);

    const int Cs[3] = {30, 128, 128};
    const int Ts[3] = {128, 128, 256};
    float* ins[3]  = {xA, xB, xA};
    float* outs[3] = {xB, xA, xB};

    for (int l = 0; l < 3; l++) {
        int C = Cs[l], T = Ts[l];
        int Kd = RA * C, N = NA * T;

        interp_kernel<<<BV * RA, (C + 31) / 32 * 32>>>(ins[l], C, bc_idx, bc_w, Ibuf);

        long tot = (long)Kd * N;
        rot_kernel<<<(int)((tot + 255) / 256), 256>>>(Kw[l], T, C, Wbuf);

        dim3 grid(N / GBN, BV / GBM);
        sgemm<<<grid, 256>>>(Ibuf, Wbuf, Gbuf, BV, N, Kd);

        amp_kernel<<<BV, T>>>(Gbuf, T, Bw[l], Gw[l], Ew[l], outs[l]);
    }

    gmax_partial<<<dim3(BATCH, 16), 256>>>(xB, Part);
    mlp_kernel<<<BATCH, 512>>>(Part, w1, c1, w2, c2, w3, c3, out);
}

// round 6
// speedup vs baseline: 2.8420x; 2.8420x over previous
#include <cuda_runtime.h>
#include <cuda_bf16.h>
#include <cstdint>
#include <math.h>

// ---------------------------------------------------------------------------
// Problem constants
// ---------------------------------------------------------------------------
#define BATCH 4
#define NV    2048
#define BV    (BATCH * NV)      // 8192
#define NR    5
#define NA    8
#define RA    (NR * NA)         // 40
#define CIN   30
#define KDMAX 5120              // RA * 128
#define NMAX  2048              // NA * 256

// ---------------------------------------------------------------------------
// PTX helpers (portable: sm_80-class tensor core path, works on sm_103 target)
// ---------------------------------------------------------------------------
__device__ __forceinline__ uint32_t smem_u32(const void* p) {
    uint32_t a;
    asm("{ .reg .u64 t; cvta.to.shared.u64 t, %1; cvt.u32.u64 %0, t; }" : "=r"(a) : "l"(p));
    return a;
}
#define CP_ASYNC_CG(dst, src) \
    asm volatile("cp.async.cg.shared.global [%0], [%1], 16;" :: "r"(dst), "l"(src))
#define CP_COMMIT() asm volatile("cp.async.commit_group;" ::: "memory")
#define CP_WAIT(n)  asm volatile("cp.async.wait_group %0;" :: "n"(n) : "memory")

#define LDSM_X4(r0, r1, r2, r3, addr) \
    asm volatile("ldmatrix.sync.aligned.m8n8.x4.shared.b16 {%0,%1,%2,%3}, [%4];" \
                 : "=r"(r0), "=r"(r1), "=r"(r2), "=r"(r3) : "r"(addr))

#define MMA_BF16(d, a0, a1, a2, a3, b0, b1) \
    asm volatile("mma.sync.aligned.m16n8k16.row.col.f32.bf16.bf16.f32 " \
                 "{%0,%1,%2,%3}, {%4,%5,%6,%7}, {%8,%9}, {%0,%1,%2,%3};" \
                 : "+f"((d)[0]), "+f"((d)[1]), "+f"((d)[2]), "+f"((d)[3]) \
                 : "r"(a0), "r"(a1), "r"(a2), "r"(a3), "r"(b0), "r"(b1))

// ---------------------------------------------------------------------------
// Scratch (device globals; no runtime allocation allowed)
// ---------------------------------------------------------------------------
__device__ __align__(256) float          g_xA[BV * 128];
__device__ __align__(256) float          g_xB[BV * 256];
__device__ __align__(256) __nv_bfloat16  g_Ah[(long)BV * KDMAX];
__device__ __align__(256) __nv_bfloat16  g_Al[(long)BV * KDMAX];
__device__ __align__(256) __nv_bfloat16  g_Wh[(long)NMAX * KDMAX];
__device__ __align__(256) __nv_bfloat16  g_Wl[(long)NMAX * KDMAX];
__device__ __align__(256) float          g_G[(long)BV * NMAX];
__device__ __align__(256) float          g_part[BATCH * 16 * 256];

// ---------------------------------------------------------------------------
// Normalization constants (Keras adaption stats)
// ---------------------------------------------------------------------------
__constant__ float c_mean[CIN] = {
    -3.7189561e-06f, 0.000286194f, 0.0020740835f, 6.5275993f, -0.0052857199f,
    10.554636f, 0.057773598f, 13.915789f, 0.060970016f, 16.840271f,
    0.0570364f, 19.415283f, 0.044104282f, 21.721455f, 0.11490919f,
    23.64683f, 0.099816084f, 25.365578f, 0.01769533f, 26.861437f,
    0.054662503f, 28.197876f, -0.0024771576f, 29.295244f, 0.039666731f,
    30.319246f, 0.0088442909f, 31.160933f, -0.026727753f, 31.874565f};
__constant__ float c_var[CIN] = {
    3.3091978e-06f, 0.00016750646f, 0.80988622f, 85135.219f, 1.5621265f,
    222580.2f, 8.812871f, 386912.78f, 10.180468f, 566622.44f,
    9.8600769f, 753158.06f, 7.8372045f, 942701.62f, 30.926426f,
    1117233.0f, 25.045353f, 1285543.9f, 6.3646226f, 1441639.1f,
    12.326629f, 1588653.4f, 6.9686499f, 1714707.9f, 10.755516f,
    1836677.8f, 8.416419f, 1940088.8f, 10.344138f, 2029969.6f};

__device__ __forceinline__ float elu1(float x) { return x > 0.0f ? x : expm1f(x); }

// ---------------------------------------------------------------------------
// 1) Input normalization
// ---------------------------------------------------------------------------
__global__ void norm_kernel(const float* __restrict__ sig, float* __restrict__ x0) {
    int i = blockIdx.x * blockDim.x + threadIdx.x;
    if (i < BV * CIN) {
        int c = i % CIN;
        x0[i] = (sig[i] - c_mean[c]) * rsqrtf(c_var[c]);
    }
}

// ---------------------------------------------------------------------------
// 2) Barycentric gather + interpolation -> split bf16 hi/lo A operand
// ---------------------------------------------------------------------------
__global__ void interp_split(const float* __restrict__ x, int C, int lda,
                             const int* __restrict__ bc_idx,
                             const float* __restrict__ bc_w,
                             __nv_bfloat16* __restrict__ Ah,
                             __nv_bfloat16* __restrict__ Al) {
    int blk = blockIdx.x;           // bv*RA + ra
    int bv  = blk / RA;
    int ra  = blk - bv * RA;
    int b   = bv >> 11;
    const int*   idx = bc_idx + (long)blk * 3;
    const float* w   = bc_w   + (long)blk * 3;
    int i0 = idx[0], i1 = idx[1], i2 = idx[2];
    float w0 = w[0], w1 = w[1], w2 = w[2];
    int c = threadIdx.x;
    if (c < C) {
        long base = (long)b * NV * C;
        float v = w0 * x[base + (long)i0 * C + c]
                + w1 * x[base + (long)i1 * C + c]
                + w2 * x[base + (long)i2 * C + c];
        __nv_bfloat16 h = __float2bfloat16(v);
        float hv = __bfloat162float(h);
        long o = (long)bv * lda + ra * C + c;
        Ah[o] = h;
        Al[o] = __float2bfloat16(v - hv);
    }
}

// ---------------------------------------------------------------------------
// 3) Rotated kernel -> transposed split bf16 B operand:
//    Wt[n = o*T+t][k = (r*8+a)*C + c] = K[r, (a-o) mod 8, t, c]
// ---------------------------------------------------------------------------
__global__ void rot_split(const float* __restrict__ Kw, int T, int C, int lda,
                          __nv_bfloat16* __restrict__ Wh,
                          __nv_bfloat16* __restrict__ Wl) {
    long i = (long)blockIdx.x * blockDim.x + threadIdx.x;
    long Kd = (long)RA * C;
    int  Nn = NA * T;
    long total = (long)Nn * Kd;
    if (i >= total) return;
    long n = i / Kd;
    long k = i - n * Kd;
    int c  = (int)(k % C);
    int ra = (int)(k / C);
    int a = ra & 7, r = ra >> 3;
    int t = (int)(n % T);
    int o = (int)(n / T);
    int as = (a - o + 8) & 7;
    float v = Kw[(((long)r * 8 + as) * T + t) * C + c];
    __nv_bfloat16 h = __float2bfloat16(v);
    float hv = __bfloat162float(h);
    long off = n * (long)lda + k;
    Wh[off] = h;
    Wl[off] = __float2bfloat16(v - hv);
}

// ---------------------------------------------------------------------------
// 4) Tensor-core GEMM via mma.sync (bf16, fp32 accum), error-compensated:
//    acc += Ah*Wh + Al*Wh + Ah*Wl
//    A: [M, ldk] K-major bf16;  W: [N, ldk] K-major bf16 (B^T layout)
//    CTA tile 128x128x32, 8 warps (warp tile 32x64), double-buffered cp.async.
//    Smem rows: 64B (32 bf16) in 4x16B chunks, XOR swizzle ch ^= (row>>1)&3.
// ---------------------------------------------------------------------------
#define MAT_BYTES 8192                  // 128 rows * 64 B
#define STAGE_BYTES (4 * MAT_BYTES)     // Ah, Al, Wh, Wl
#define GEMM_SMEM (2 * STAGE_BYTES)     // 65536

__device__ __forceinline__ uint32_t swz(int row, int ch) {
    return (uint32_t)(row * 64 + ((ch ^ ((row >> 1) & 3)) << 4));
}

__global__ void __launch_bounds__(256, 2) gemm_mma(
    const __nv_bfloat16* __restrict__ Ah, const __nv_bfloat16* __restrict__ Al,
    const __nv_bfloat16* __restrict__ Wh, const __nv_bfloat16* __restrict__ Wl,
    float* __restrict__ Cout, int N, int ldk)
{
    extern __shared__ char smem[];
    const uint32_t sb = smem_u32(smem);
    const int tid = threadIdx.x, lane = tid & 31, wid = tid >> 5;
    const int wm = (wid & 3) * 32;        // warp m offset in tile
    const int wn = (wid >> 2) * 64;       // warp n offset in tile
    const long m0 = (long)blockIdx.y * 128;
    const long n0 = (long)blockIdx.x * 128;

    // loader mapping: 8 cp.async per thread per stage
    const int lr  = (tid >> 2) & 63;      // row base (0..63)
    const int lch = tid & 3;              // 16B chunk
    const __nv_bfloat16* gbase[4] = {Ah, Al, Wh, Wl};

    float acc[2][8][4];
#pragma unroll
    for (int i = 0; i < 2; i++)
#pragma unroll
        for (int j = 0; j < 8; j++)
#pragma unroll
            for (int q = 0; q < 4; q++) acc[i][j][q] = 0.0f;

    const int nk = ldk >> 5;  // BK = 32

    // ldmatrix per-lane row/chunk components
    const int a_row = wm + ((lane >> 3) & 1) * 8 + (lane & 7);
    const int a_chs = lane >> 4;              // chunk sub-index (0/1)
    const int b_row = wn + ((lane >> 4) & 1) * 8 + (lane & 7);
    const int b_chs = (lane >> 3) & 1;

    // ---- prologue: load stage 0
    {
        const long k0 = 0;
#pragma unroll
        for (int it = 0; it < 8; it++) {
            int mat = it >> 1;
            int row = lr + (it & 1) * 64;
            long grow = (mat < 2 ? m0 : n0) + row;
            const __nv_bfloat16* g = gbase[mat] + grow * ldk + k0 + lch * 8;
            uint32_t dst = sb + mat * MAT_BYTES + swz(row, lch);
            CP_ASYNC_CG(dst, g);
        }
        CP_COMMIT();
    }

    for (int j = 0; j < nk; j++) {
        int s = j & 1;
        if (j + 1 < nk) {
            const long k0 = (long)(j + 1) << 5;
            uint32_t stg = sb + ((j + 1) & 1) * STAGE_BYTES;
#pragma unroll
            for (int it = 0; it < 8; it++) {
                int mat = it >> 1;
                int row = lr + (it & 1) * 64;
                long grow = (mat < 2 ? m0 : n0) + row;
                const __nv_bfloat16* g = gbase[mat] + grow * ldk + k0 + lch * 8;
                uint32_t dst = stg + mat * MAT_BYTES + swz(row, lch);
                CP_ASYNC_CG(dst, g);
            }
            CP_COMMIT();
            CP_WAIT(1);
        } else {
            CP_WAIT(0);
        }
        __syncthreads();

        const uint32_t base = sb + s * STAGE_BYTES;
#pragma unroll
        for (int kg = 0; kg < 2; kg++) {
            uint32_t ah[2][4], al[2][4];
#pragma unroll
            for (int mg = 0; mg < 2; mg++) {
                int row = a_row + mg * 16;
                int ch = 2 * kg + a_chs;
                uint32_t addr = base + swz(row, ch);
                LDSM_X4(ah[mg][0], ah[mg][1], ah[mg][2], ah[mg][3], addr);
                LDSM_X4(al[mg][0], al[mg][1], al[mg][2], al[mg][3], addr + MAT_BYTES);
            }
#pragma unroll
            for (int p = 0; p < 4; p++) {
                int row = b_row + p * 16;
                int ch = 2 * kg + b_chs;
                uint32_t baddr = base + 2 * MAT_BYTES + swz(row, ch);
                uint32_t bh0, bh1, bh2, bh3, bl0, bl1, bl2, bl3;
                LDSM_X4(bh0, bh1, bh2, bh3, baddr);
                LDSM_X4(bl0, bl1, bl2, bl3, baddr + MAT_BYTES);
#pragma unroll
                for (int mg = 0; mg < 2; mg++) {
                    MMA_BF16(acc[mg][2 * p],     ah[mg][0], ah[mg][1], ah[mg][2], ah[mg][3], bh0, bh1);
                    MMA_BF16(acc[mg][2 * p],     al[mg][0], al[mg][1], al[mg][2], al[mg][3], bh0, bh1);
                    MMA_BF16(acc[mg][2 * p],     ah[mg][0], ah[mg][1], ah[mg][2], ah[mg][3], bl0, bl1);
                    MMA_BF16(acc[mg][2 * p + 1], ah[mg][0], ah[mg][1], ah[mg][2], ah[mg][3], bh2, bh3);
                    MMA_BF16(acc[mg][2 * p + 1], al[mg][0], al[mg][1], al[mg][2], al[mg][3], bh2, bh3);
                    MMA_BF16(acc[mg][2 * p + 1], ah[mg][0], ah[mg][1], ah[mg][2], ah[mg][3], bl2, bl3);
                }
            }
        }
        __syncthreads();
    }

    // ---- epilogue: write fp32 accumulators
    const int erow = lane >> 2;
    const int ecol = 2 * (lane & 3);
#pragma unroll
    for (int mg = 0; mg < 2; mg++) {
#pragma unroll
        for (int g = 0; g < 8; g++) {
            long row = m0 + wm + mg * 16 + erow;
            long col = n0 + wn + g * 8 + ecol;
            float2 v0 = make_float2(acc[mg][g][0], acc[mg][g][1]);
            float2 v1 = make_float2(acc[mg][g][2], acc[mg][g][3]);
            *(float2*)(Cout + row * N + col) = v0;
            *(float2*)(Cout + (row + 8) * N + col) = v1;
        }
    }
}

// ---------------------------------------------------------------------------
// 5) Epilogue: bias + ELU, angular max pooling, BN
// ---------------------------------------------------------------------------
__global__ void amp_kernel(const float* __restrict__ gout, int T,
                           const float* __restrict__ bias,
                           const float* __restrict__ gamma,
                           const float* __restrict__ beta,
                           float* __restrict__ xnext) {
    __shared__ float s[NA * 256];
    int bv = blockIdx.x;
    int t  = threadIdx.x;
    int bd = blockDim.x;   // == T
    const float* row = gout + (long)bv * NA * T;
    float y[NA];
#pragma unroll
    for (int o = 0; o < NA; o++) {
        float v = row[o * T + t] + bias[t];
        v = elu1(v);
        y[o] = v;
        s[o * bd + t] = v * v;
    }
    __syncthreads();
    for (int stride = bd >> 1; stride > 0; stride >>= 1) {
        if (t < stride) {
#pragma unroll
            for (int o = 0; o < NA; o++)
                s[o * bd + t] += s[o * bd + t + stride];
        }
        __syncthreads();
    }
    int best = 0;
    float bn = s[0];
#pragma unroll
    for (int o = 1; o < NA; o++) {
        float v = s[o * bd];
        if (v > bn) { bn = v; best = o; }
    }
    float scale = rsqrtf(1.0f + 1e-3f);
    xnext[(long)bv * T + t] = gamma[t] * y[best] * scale + beta[t];
}

// ---------------------------------------------------------------------------
// 6) Global max pool partials
// ---------------------------------------------------------------------------
__global__ void gmax_partial(const float* __restrict__ x, float* __restrict__ part) {
    int b = blockIdx.x, ch = blockIdx.y, t = threadIdx.x;
    float m = -3.4e38f;
    int v0 = ch * (NV / 16);
    for (int v = v0; v < v0 + NV / 16; v++)
        m = fmaxf(m, x[((long)(b * NV + v)) * 256 + t]);
    part[(b * 16 + ch) * 256 + t] = m;
}

// ---------------------------------------------------------------------------
// 7) MLP head
// ---------------------------------------------------------------------------
__global__ void mlp_kernel(const float* __restrict__ part,
                           const float* __restrict__ w1, const float* __restrict__ c1,
                           const float* __restrict__ w2, const float* __restrict__ c2,
                           const float* __restrict__ w3, const float* __restrict__ c3,
                           float* __restrict__ out) {
    int b = blockIdx.x, tid = threadIdx.x;  // 512 threads
    __shared__ float h0[256], h1[512], h2[256];
    if (tid < 256) {
        float m = -3.4e38f;
        for (int ch = 0; ch < 16; ch++)
            m = fmaxf(m, part[(b * 16 + ch) * 256 + tid]);
        h0[tid] = m;
    }
    __syncthreads();
    {
        float acc = c1[tid];
        for (int k = 0; k < 256; k++) acc += h0[k] * w1[k * 512 + tid];
        h1[tid] = elu1(acc);
    }
    __syncthreads();
    if (tid < 256) {
        float acc = c2[tid];
        for (int k = 0; k < 512; k++) acc += h1[k] * w2[k * 256 + tid];
        h2[tid] = elu1(acc);
    }
    __syncthreads();
    if (tid < 40) {
        float acc = c3[tid];
        for (int k = 0; k < 256; k++) acc += h2[k] * w3[k * 40 + tid];
        out[b * 40 + tid] = acc;
    }
}

// ---------------------------------------------------------------------------
// Launch
// ---------------------------------------------------------------------------
extern "C" void kernel_launch(void* const* d_in, const int* in_sizes, int n_in,
                              void* d_out, int out_size) {
    const float* signal = (const float*)d_in[0];
    const int*   bc_idx = (const int*)  d_in[1];
    const float* bc_w   = (const float*)d_in[2];
    const float* Kw[3]  = {(const float*)d_in[3],  (const float*)d_in[7],  (const float*)d_in[11]};
    const float* Bw[3]  = {(const float*)d_in[4],  (const float*)d_in[8],  (const float*)d_in[12]};
    const float* Gw[3]  = {(const float*)d_in[5],  (const float*)d_in[9],  (const float*)d_in[13]};
    const float* Ew[3]  = {(const float*)d_in[6],  (const float*)d_in[10], (const float*)d_in[14]};
    const float* w1 = (const float*)d_in[15]; const float* c1 = (const float*)d_in[16];
    const float* w2 = (const float*)d_in[17]; const float* c2 = (const float*)d_in[18];
    const float* w3 = (const float*)d_in[19]; const float* c3 = (const float*)d_in[20];
    float* out = (float*)d_out;

    float *xA, *xB, *Gbuf, *Part;
    __nv_bfloat16 *Ah, *Al, *Wh, *Wl;
    cudaGetSymbolAddress((void**)&xA,   g_xA);
    cudaGetSymbolAddress((void**)&xB,   g_xB);
    cudaGetSymbolAddress((void**)&Ah,   g_Ah);
    cudaGetSymbolAddress((void**)&Al,   g_Al);
    cudaGetSymbolAddress((void**)&Wh,   g_Wh);
    cudaGetSymbolAddress((void**)&Wl,   g_Wl);
    cudaGetSymbolAddress((void**)&Gbuf, g_G);
    cudaGetSymbolAddress((void**)&Part, g_part);

    cudaFuncSetAttribute(gemm_mma, cudaFuncAttributeMaxDynamicSharedMemorySize, GEMM_SMEM);

    norm_kernel<<<(BV * CIN + 255) / 256, 256>>>(signal, xA);

    const int Cs[3]  = {30, 128, 128};
    const int Ts[3]  = {128, 128, 256};
    const int Kdp[3] = {1216, 5120, 5120};   // padded to multiple of 32
    float* ins[3]  = {xA, xB, xA};
    float* outs[3] = {xB, xA, xB};

    for (int l = 0; l < 3; l++) {
        int C = Cs[l], T = Ts[l], lda = Kdp[l];
        int Kd = RA * C, N = NA * T;

        if (l == 0) {
            // zero K-padding region (Kd=1200 -> lda=1216)
            cudaMemsetAsync(Ah, 0, (size_t)BV * lda * sizeof(__nv_bfloat16));
            cudaMemsetAsync(Al, 0, (size_t)BV * lda * sizeof(__nv_bfloat16));
            cudaMemsetAsync(Wh, 0, (size_t)N * lda * sizeof(__nv_bfloat16));
            cudaMemsetAsync(Wl, 0, (size_t)N * lda * sizeof(__nv_bfloat16));
        }

        interp_split<<<BV * RA, (C + 31) / 32 * 32>>>(ins[l], C, lda, bc_idx, bc_w, Ah, Al);

        long tot = (long)N * Kd;
        rot_split<<<(int)((tot + 255) / 256), 256>>>(Kw[l], T, C, lda, Wh, Wl);

        dim3 grid(N / 128, BV / 128);
        gemm_mma<<<grid, 256, GEMM_SMEM>>>(Ah, Al, Wh, Wl, Gbuf, N, lda);

        amp_kernel<<<BV, T>>>(Gbuf, T, Bw[l], Gw[l], Ew[l], outs[l]);
    }

    gmax_partial<<<dim3(BATCH, 16), 256>>>(xB, Part);
    mlp_kernel<<<BATCH, 512>>>(Part, w1, c1, w2, c2, w3, c3, out);
}

// round 8
// speedup vs baseline: 3.4937x; 1.2293x over previous
#include <cuda_runtime.h>
#include <cuda_bf16.h>
#include <cstdint>
#include <math.h>

// ---------------------------------------------------------------------------
// Problem constants
// ---------------------------------------------------------------------------
#define BATCH 4
#define NV    2048
#define BV    (BATCH * NV)      // 8192
#define NR    5
#define NA    8
#define RA    (NR * NA)         // 40
#define CIN   30
#define KDMAX 5120              // RA * 128
#define NMAX  2048              // NA * 256

// ---------------------------------------------------------------------------
// PTX helpers (portable: sm_80-class tensor core path, works on sm_103 target)
// ---------------------------------------------------------------------------
__device__ __forceinline__ uint32_t smem_u32(const void* p) {
    uint32_t a;
    asm("{ .reg .u64 t; cvta.to.shared.u64 t, %1; cvt.u32.u64 %0, t; }" : "=r"(a) : "l"(p));
    return a;
}
#define CP_ASYNC_CG(dst, src) \
    asm volatile("cp.async.cg.shared.global [%0], [%1], 16;" :: "r"(dst), "l"(src))
#define CP_COMMIT() asm volatile("cp.async.commit_group;" ::: "memory")
#define CP_WAIT(n)  asm volatile("cp.async.wait_group %0;" :: "n"(n) : "memory")

#define LDSM_X4(r0, r1, r2, r3, addr) \
    asm volatile("ldmatrix.sync.aligned.m8n8.x4.shared.b16 {%0,%1,%2,%3}, [%4];" \
                 : "=r"(r0), "=r"(r1), "=r"(r2), "=r"(r3) : "r"(addr))

#define MMA_BF16(d, a0, a1, a2, a3, b0, b1) \
    asm volatile("mma.sync.aligned.m16n8k16.row.col.f32.bf16.bf16.f32 " \
                 "{%0,%1,%2,%3}, {%4,%5,%6,%7}, {%8,%9}, {%0,%1,%2,%3};" \
                 : "+f"((d)[0]), "+f"((d)[1]), "+f"((d)[2]), "+f"((d)[3]) \
                 : "r"(a0), "r"(a1), "r"(a2), "r"(a3), "r"(b0), "r"(b1))

// ---------------------------------------------------------------------------
// Scratch (device globals; no runtime allocation allowed)
// ---------------------------------------------------------------------------
__device__ __align__(256) float          g_xA[BV * 128];
__device__ __align__(256) float          g_xB[BV * 256];
__device__ __align__(256) __nv_bfloat16  g_Ah[(long)BV * KDMAX];
__device__ __align__(256) __nv_bfloat16  g_Al[(long)BV * KDMAX];
__device__ __align__(256) __nv_bfloat16  g_Wh[(long)NMAX * KDMAX];
__device__ __align__(256) __nv_bfloat16  g_Wl[(long)NMAX * KDMAX];
__device__ __align__(256) float          g_G[(long)BV * NMAX];
__device__ __align__(256) float          g_part[BATCH * 16 * 256];

// ---------------------------------------------------------------------------
// Normalization constants (Keras adaption stats)
// ---------------------------------------------------------------------------
__constant__ float c_mean[CIN] = {
    -3.7189561e-06f, 0.000286194f, 0.0020740835f, 6.5275993f, -0.0052857199f,
    10.554636f, 0.057773598f, 13.915789f, 0.060970016f, 16.840271f,
    0.0570364f, 19.415283f, 0.044104282f, 21.721455f, 0.11490919f,
    23.64683f, 0.099816084f, 25.365578f, 0.01769533f, 26.861437f,
    0.054662503f, 28.197876f, -0.0024771576f, 29.295244f, 0.039666731f,
    30.319246f, 0.0088442909f, 31.160933f, -0.026727753f, 31.874565f};
__constant__ float c_var[CIN] = {
    3.3091978e-06f, 0.00016750646f, 0.80988622f, 85135.219f, 1.5621265f,
    222580.2f, 8.812871f, 386912.78f, 10.180468f, 566622.44f,
    9.8600769f, 753158.06f, 7.8372045f, 942701.62f, 30.926426f,
    1117233.0f, 25.045353f, 1285543.9f, 6.3646226f, 1441639.1f,
    12.326629f, 1588653.4f, 6.9686499f, 1714707.9f, 10.755516f,
    1836677.8f, 8.416419f, 1940088.8f, 10.344138f, 2029969.6f};

__device__ __forceinline__ float elu1(float x) { return x > 0.0f ? x : expm1f(x); }

// ---------------------------------------------------------------------------
// 1) Input normalization -> padded [BV, 32] (channels 30,31 = 0)
// ---------------------------------------------------------------------------
__global__ void norm_kernel(const float* __restrict__ sig, float* __restrict__ x0) {
    int i = blockIdx.x * blockDim.x + threadIdx.x;
    if (i < BV * 32) {
        int c = i & 31, bv = i >> 5;
        x0[i] = (c < CIN) ? (sig[bv * CIN + c] - c_mean[c]) * rsqrtf(c_var[c]) : 0.0f;
    }
}

// ---------------------------------------------------------------------------
// 2) Barycentric gather + interp -> split bf16 hi/lo A. One block per vertex,
//    idx/w staged in smem, float4 gathers, packed 8-B bf16x4 stores.
// ---------------------------------------------------------------------------
__global__ void __launch_bounds__(128) interp_v4(
    const float* __restrict__ x, int Cp, int c4log, int lda,
    const int* __restrict__ bc_idx, const float* __restrict__ bc_w,
    __nv_bfloat16* __restrict__ Ah, __nv_bfloat16* __restrict__ Al)
{
    __shared__ int   sidx[RA * 3];
    __shared__ float sw[RA * 3];
    const int bv  = blockIdx.x;
    const int tid = threadIdx.x;
    if (tid < RA * 3) {
        sidx[tid] = bc_idx[bv * RA * 3 + tid];
        sw[tid]   = bc_w[bv * RA * 3 + tid];
    }
    __syncthreads();
    const int C4 = 1 << c4log;          // Cp/4
    const int total = RA << c4log;
    const long xbase = (long)(bv >> 11) << 11;   // b*NV
    for (int u = tid; u < total; u += 128) {
        int ra = u >> c4log;
        int c4 = u & (C4 - 1);
        int i0 = sidx[ra * 3], i1 = sidx[ra * 3 + 1], i2 = sidx[ra * 3 + 2];
        float w0 = sw[ra * 3], w1 = sw[ra * 3 + 1], w2 = sw[ra * 3 + 2];
        const float4* r0 = (const float4*)(x + (xbase + i0) * Cp);
        const float4* r1 = (const float4*)(x + (xbase + i1) * Cp);
        const float4* r2 = (const float4*)(x + (xbase + i2) * Cp);
        float4 a = r0[c4], b = r1[c4], c = r2[c4];
        float4 v;
        v.x = w0 * a.x + w1 * b.x + w2 * c.x;
        v.y = w0 * a.y + w1 * b.y + w2 * c.y;
        v.z = w0 * a.z + w1 * b.z + w2 * c.z;
        v.w = w0 * a.w + w1 * b.w + w2 * c.w;
        __nv_bfloat16 hx = __float2bfloat16(v.x), hy = __float2bfloat16(v.y);
        __nv_bfloat16 hz = __float2bfloat16(v.z), hw = __float2bfloat16(v.w);
        union { __nv_bfloat162 b2[2]; uint2 u2; } hi, lo;
        hi.b2[0] = __halves2bfloat162(hx, hy);
        hi.b2[1] = __halves2bfloat162(hz, hw);
        lo.b2[0] = __halves2bfloat162(__float2bfloat16(v.x - __bfloat162float(hx)),
                                      __float2bfloat16(v.y - __bfloat162float(hy)));
        lo.b2[1] = __halves2bfloat162(__float2bfloat16(v.z - __bfloat162float(hz)),
                                      __float2bfloat16(v.w - __bfloat162float(hw)));
        long off = (long)bv * lda + ra * Cp + c4 * 4;
        *(uint2*)(Ah + off) = hi.u2;
        *(uint2*)(Al + off) = lo.u2;
    }
}

// ---------------------------------------------------------------------------
// 3a) Rotated kernel -> transposed split bf16 B (vector, C multiple of 4):
//     Wt[n][ra*C + c] = K[r, (a - n/T) mod 8, n%T, c]
// ---------------------------------------------------------------------------
__global__ void __launch_bounds__(128) rot_v4(
    const float* __restrict__ Kw, int Tlog, int C, int c4log, int lda,
    __nv_bfloat16* __restrict__ Wh, __nv_bfloat16* __restrict__ Wl)
{
    const int n = blockIdx.x;
    const int t = n & ((1 << Tlog) - 1);
    const int o = n >> Tlog;
    const int C4 = 1 << c4log;
    const int total = RA << c4log;
    for (int u = threadIdx.x; u < total; u += 128) {
        int ra = u >> c4log, c4 = u & (C4 - 1);
        int a = ra & 7, r = ra >> 3;
        int as = (a - o + 8) & 7;
        const float4* src = (const float4*)(Kw + (long)((((r << 3) + as) << Tlog) + t) * C);
        float4 v = src[c4];
        __nv_bfloat16 hx = __float2bfloat16(v.x), hy = __float2bfloat16(v.y);
        __nv_bfloat16 hz = __float2bfloat16(v.z), hw = __float2bfloat16(v.w);
        union { __nv_bfloat162 b2[2]; uint2 u2; } hi, lo;
        hi.b2[0] = __halves2bfloat162(hx, hy);
        hi.b2[1] = __halves2bfloat162(hz, hw);
        lo.b2[0] = __halves2bfloat162(__float2bfloat16(v.x - __bfloat162float(hx)),
                                      __float2bfloat16(v.y - __bfloat162float(hy)));
        lo.b2[1] = __halves2bfloat162(__float2bfloat16(v.z - __bfloat162float(hz)),
                                      __float2bfloat16(v.w - __bfloat162float(hw)));
        long off = (long)n * lda + ra * C + c4 * 4;
        *(uint2*)(Wh + off) = hi.u2;
        *(uint2*)(Wl + off) = lo.u2;
    }
}

// ---------------------------------------------------------------------------
// 3b) Rotated kernel, scalar variant for layer 0 (C=30 real, Cp=32 padded)
// ---------------------------------------------------------------------------
__global__ void __launch_bounds__(128) rot_sc(
    const float* __restrict__ Kw, int Tlog, int lda,
    __nv_bfloat16* __restrict__ Wh, __nv_bfloat16* __restrict__ Wl)
{
    const int n = blockIdx.x;
    const int t = n & ((1 << Tlog) - 1);
    const int o = n >> Tlog;
    const int total = RA * 32;
    for (int u = threadIdx.x; u < total; u += 128) {
        int ra = u >> 5, c = u & 31;
        int a = ra & 7, r = ra >> 3;
        int as = (a - o + 8) & 7;
        float v = (c < CIN) ? Kw[(long)((((r << 3) + as) << Tlog) + t) * CIN + c] : 0.0f;
        __nv_bfloat16 h = __float2bfloat16(v);
        long off = (long)n * lda + ra * 32 + c;
        Wh[off] = h;
        Wl[off] = __float2bfloat16(v - __bfloat162float(h));
    }
}

// ---------------------------------------------------------------------------
// 4) Tensor-core GEMM via mma.sync (bf16, fp32 accum), error-compensated:
//    acc += Ah*Wh + Al*Wh + Ah*Wl  (unchanged from R6-passing version)
// ---------------------------------------------------------------------------
#define MAT_BYTES 8192                  // 128 rows * 64 B
#define STAGE_BYTES (4 * MAT_BYTES)     // Ah, Al, Wh, Wl
#define GEMM_SMEM (2 * STAGE_BYTES)     // 65536

__device__ __forceinline__ uint32_t swz(int row, int ch) {
    return (uint32_t)(row * 64 + ((ch ^ ((row >> 1) & 3)) << 4));
}

__global__ void __launch_bounds__(256, 2) gemm_mma(
    const __nv_bfloat16* __restrict__ Ah, const __nv_bfloat16* __restrict__ Al,
    const __nv_bfloat16* __restrict__ Wh, const __nv_bfloat16* __restrict__ Wl,
    float* __restrict__ Cout, int N, int ldk)
{
    extern __shared__ char smem[];
    const uint32_t sb = smem_u32(smem);
    const int tid = threadIdx.x, lane = tid & 31, wid = tid >> 5;
    const int wm = (wid & 3) * 32;
    const int wn = (wid >> 2) * 64;
    const long m0 = (long)blockIdx.y * 128;
    const long n0 = (long)blockIdx.x * 128;

    const int lr  = (tid >> 2) & 63;
    const int lch = tid & 3;
    const __nv_bfloat16* gbase[4] = {Ah, Al, Wh, Wl};

    float acc[2][8][4];
#pragma unroll
    for (int i = 0; i < 2; i++)
#pragma unroll
        for (int j = 0; j < 8; j++)
#pragma unroll
            for (int q = 0; q < 4; q++) acc[i][j][q] = 0.0f;

    const int nk = ldk >> 5;

    const int a_row = wm + ((lane >> 3) & 1) * 8 + (lane & 7);
    const int a_chs = lane >> 4;
    const int b_row = wn + ((lane >> 4) & 1) * 8 + (lane & 7);
    const int b_chs = (lane >> 3) & 1;

    {
        const long k0 = 0;
#pragma unroll
        for (int it = 0; it < 8; it++) {
            int mat = it >> 1;
            int row = lr + (it & 1) * 64;
            long grow = (mat < 2 ? m0 : n0) + row;
            const __nv_bfloat16* g = gbase[mat] + grow * ldk + k0 + lch * 8;
            uint32_t dst = sb + mat * MAT_BYTES + swz(row, lch);
            CP_ASYNC_CG(dst, g);
        }
        CP_COMMIT();
    }

    for (int j = 0; j < nk; j++) {
        int s = j & 1;
        if (j + 1 < nk) {
            const long k0 = (long)(j + 1) << 5;
            uint32_t stg = sb + ((j + 1) & 1) * STAGE_BYTES;
#pragma unroll
            for (int it = 0; it < 8; it++) {
                int mat = it >> 1;
                int row = lr + (it & 1) * 64;
                long grow = (mat < 2 ? m0 : n0) + row;
                const __nv_bfloat16* g = gbase[mat] + grow * ldk + k0 + lch * 8;
                uint32_t dst = stg + mat * MAT_BYTES + swz(row, lch);
                CP_ASYNC_CG(dst, g);
            }
            CP_COMMIT();
            CP_WAIT(1);
        } else {
            CP_WAIT(0);
        }
        __syncthreads();

        const uint32_t base = sb + s * STAGE_BYTES;
#pragma unroll
        for (int kg = 0; kg < 2; kg++) {
            uint32_t ah[2][4], al[2][4];
#pragma unroll
            for (int mg = 0; mg < 2; mg++) {
                int row = a_row + mg * 16;
                int ch = 2 * kg + a_chs;
                uint32_t addr = base + swz(row, ch);
                LDSM_X4(ah[mg][0], ah[mg][1], ah[mg][2], ah[mg][3], addr);
                LDSM_X4(al[mg][0], al[mg][1], al[mg][2], al[mg][3], addr + MAT_BYTES);
            }
#pragma unroll
            for (int p = 0; p < 4; p++) {
                int row = b_row + p * 16;
                int ch = 2 * kg + b_chs;
                uint32_t baddr = base + 2 * MAT_BYTES + swz(row, ch);
                uint32_t bh0, bh1, bh2, bh3, bl0, bl1, bl2, bl3;
                LDSM_X4(bh0, bh1, bh2, bh3, baddr);
                LDSM_X4(bl0, bl1, bl2, bl3, baddr + MAT_BYTES);
#pragma unroll
                for (int mg = 0; mg < 2; mg++) {
                    MMA_BF16(acc[mg][2 * p],     ah[mg][0], ah[mg][1], ah[mg][2], ah[mg][3], bh0, bh1);
                    MMA_BF16(acc[mg][2 * p],     al[mg][0], al[mg][1], al[mg][2], al[mg][3], bh0, bh1);
                    MMA_BF16(acc[mg][2 * p],     ah[mg][0], ah[mg][1], ah[mg][2], ah[mg][3], bl0, bl1);
                    MMA_BF16(acc[mg][2 * p + 1], ah[mg][0], ah[mg][1], ah[mg][2], ah[mg][3], bh2, bh3);
                    MMA_BF16(acc[mg][2 * p + 1], al[mg][0], al[mg][1], al[mg][2], al[mg][3], bh2, bh3);
                    MMA_BF16(acc[mg][2 * p + 1], ah[mg][0], ah[mg][1], ah[mg][2], ah[mg][3], bl2, bl3);
                }
            }
        }
        __syncthreads();
    }

    const int erow = lane >> 2;
    const int ecol = 2 * (lane & 3);
#pragma unroll
    for (int mg = 0; mg < 2; mg++) {
#pragma unroll
        for (int g = 0; g < 8; g++) {
            long row = m0 + wm + mg * 16 + erow;
            long col = n0 + wn + g * 8 + ecol;
            float2 v0 = make_float2(acc[mg][g][0], acc[mg][g][1]);
            float2 v1 = make_float2(acc[mg][g][2], acc[mg][g][3]);
            *(float2*)(Cout + row * N + col) = v0;
            *(float2*)(Cout + (row + 8) * N + col) = v1;
        }
    }
}

// ---------------------------------------------------------------------------
// 5) Epilogue: bias + ELU, angular max pooling, BN — one warp per vertex
// ---------------------------------------------------------------------------
__global__ void __launch_bounds__(256) amp_warp(
    const float* __restrict__ G, int T,
    const float* __restrict__ bias, const float* __restrict__ gamma,
    const float* __restrict__ beta, float* __restrict__ xnext)
{
    const int gw   = (blockIdx.x * blockDim.x + threadIdx.x) >> 5;  // vertex
    const int lane = threadIdx.x & 31;
    if (gw >= BV) return;
    const int C4T = T >> 2;
    const int nj  = C4T >> 5;   // 1 (T=128) or 2 (T=256)
    const float4* row = (const float4*)(G + (long)gw * NA * T);
    const float4* b4  = (const float4*)bias;
    int besto = 0; float bestn = -1.0f;
#pragma unroll
    for (int o = 0; o < NA; o++) {
        float s = 0.0f;
        for (int j = 0; j < nj; j++) {
            int c4 = lane + j * 32;
            float4 v = row[o * C4T + c4];
            float4 bb = b4[c4];
            float e0 = elu1(v.x + bb.x), e1 = elu1(v.y + bb.y);
            float e2 = elu1(v.z + bb.z), e3 = elu1(v.w + bb.w);
            s += e0 * e0 + e1 * e1 + e2 * e2 + e3 * e3;
        }
        s += __shfl_xor_sync(0xffffffffu, s, 16);
        s += __shfl_xor_sync(0xffffffffu, s, 8);
        s += __shfl_xor_sync(0xffffffffu, s, 4);
        s += __shfl_xor_sync(0xffffffffu, s, 2);
        s += __shfl_xor_sync(0xffffffffu, s, 1);
        if (s > bestn) { bestn = s; besto = o; }
    }
    const float scale = rsqrtf(1.0f + 1e-3f);
    const float4* g4  = (const float4*)gamma;
    const float4* be4 = (const float4*)beta;
    float4* out4 = (float4*)(xnext + (long)gw * T);
    for (int j = 0; j < nj; j++) {
        int c4 = lane + j * 32;
        float4 v = row[besto * C4T + c4];
        float4 bb = b4[c4], gg = g4[c4], ee = be4[c4];
        float4 r;
        r.x = gg.x * elu1(v.x + bb.x) * scale + ee.x;
        r.y = gg.y * elu1(v.y + bb.y) * scale + ee.y;
        r.z = gg.z * elu1(v.z + bb.z) * scale + ee.z;
        r.w = gg.w * elu1(v.w + bb.w) * scale + ee.w;
        out4[c4] = r;
    }
}

// ---------------------------------------------------------------------------
// 6) Global max pool partials (float4)
// ---------------------------------------------------------------------------
__global__ void gmax_v4(const float* __restrict__ x, float* __restrict__ part) {
    int b = blockIdx.x, ch = blockIdx.y, c4 = threadIdx.x;   // 64 threads
    const float4* x4 = (const float4*)x + (long)(b * NV + ch * 128) * 64;
    float4 m = make_float4(-3.4e38f, -3.4e38f, -3.4e38f, -3.4e38f);
    for (int v = 0; v < 128; v++) {
        float4 val = x4[(long)v * 64 + c4];
        m.x = fmaxf(m.x, val.x); m.y = fmaxf(m.y, val.y);
        m.z = fmaxf(m.z, val.z); m.w = fmaxf(m.w, val.w);
    }
    ((float4*)part)[(b * 16 + ch) * 64 + c4] = m;
}

// ---------------------------------------------------------------------------
// 7) MLP head
// ---------------------------------------------------------------------------
__global__ void mlp_kernel(const float* __restrict__ part,
                           const float* __restrict__ w1, const float* __restrict__ c1,
                           const float* __restrict__ w2, const float* __restrict__ c2,
                           const float* __restrict__ w3, const float* __restrict__ c3,
                           float* __restrict__ out) {
    int b = blockIdx.x, tid = threadIdx.x;  // 512 threads
    __shared__ float h0[256], h1[512], h2[256];
    if (tid < 256) {
        float m = -3.4e38f;
        for (int ch = 0; ch < 16; ch++)
            m = fmaxf(m, part[(b * 16 + ch) * 256 + tid]);
        h0[tid] = m;
    }
    __syncthreads();
    {
        float acc = c1[tid];
        for (int k = 0; k < 256; k++) acc += h0[k] * w1[k * 512 + tid];
        h1[tid] = elu1(acc);
    }
    __syncthreads();
    if (tid < 256) {
        float acc = c2[tid];
        for (int k = 0; k < 512; k++) acc += h1[k] * w2[k * 256 + tid];
        h2[tid] = elu1(acc);
    }
    __syncthreads();
    if (tid < 40) {
        float acc = c3[tid];
        for (int k = 0; k < 256; k++) acc += h2[k] * w3[k * 40 + tid];
        out[b * 40 + tid] = acc;
    }
}

// ---------------------------------------------------------------------------
// Launch
// ---------------------------------------------------------------------------
extern "C" void kernel_launch(void* const* d_in, const int* in_sizes, int n_in,
                              void* d_out, int out_size) {
    const float* signal = (const float*)d_in[0];
    const int*   bc_idx = (const int*)  d_in[1];
    const float* bc_w   = (const float*)d_in[2];
    const float* Kw[3]  = {(const float*)d_in[3],  (const float*)d_in[7],  (const float*)d_in[11]};
    const float* Bw[3]  = {(const float*)d_in[4],  (const float*)d_in[8],  (const float*)d_in[12]};
    const float* Gw[3]  = {(const float*)d_in[5],  (const float*)d_in[9],  (const float*)d_in[13]};
    const float* Ew[3]  = {(const float*)d_in[6],  (const float*)d_in[10], (const float*)d_in[14]};
    const float* w1 = (const float*)d_in[15]; const float* c1 = (const float*)d_in[16];
    const float* w2 = (const float*)d_in[17]; const float* c2 = (const float*)d_in[18];
    const float* w3 = (const float*)d_in[19]; const float* c3 = (const float*)d_in[20];
    float* out = (float*)d_out;

    float *xA, *xB, *Gbuf, *Part;
    __nv_bfloat16 *Ah, *Al, *Wh, *Wl;
    cudaGetSymbolAddress((void**)&xA,   g_xA);
    cudaGetSymbolAddress((void**)&xB,   g_xB);
    cudaGetSymbolAddress((void**)&Ah,   g_Ah);
    cudaGetSymbolAddress((void**)&Al,   g_Al);
    cudaGetSymbolAddress((void**)&Wh,   g_Wh);
    cudaGetSymbolAddress((void**)&Wl,   g_Wl);
    cudaGetSymbolAddress((void**)&Gbuf, g_G);
    cudaGetSymbolAddress((void**)&Part, g_part);

    cudaFuncSetAttribute(gemm_mma, cudaFuncAttributeMaxDynamicSharedMemorySize, GEMM_SMEM);

    norm_kernel<<<(BV * 32 + 255) / 256, 256>>>(signal, xA);

    const int Cp[3]    = {32, 128, 128};   // padded channels
    const int c4log[3] = {3, 5, 5};
    const int Ts[3]    = {128, 128, 256};
    const int Tlog[3]  = {7, 7, 8};
    const int Kdp[3]   = {1280, 5120, 5120};
    float* ins[3]  = {xA, xB, xA};
    float* outs[3] = {xB, xA, xB};

    for (int l = 0; l < 3; l++) {
        int T = Ts[l], lda = Kdp[l];
        int N = NA * T;

        interp_v4<<<BV, 128>>>(ins[l], Cp[l], c4log[l], lda, bc_idx, bc_w, Ah, Al);

        if (l == 0)
            rot_sc<<<N, 128>>>(Kw[l], Tlog[l], lda, Wh, Wl);
        else
            rot_v4<<<N, 128>>>(Kw[l], Tlog[l], Cp[l], c4log[l], lda, Wh, Wl);

        dim3 grid(N / 128, BV / 128);
        gemm_mma<<<grid, 256, GEMM_SMEM>>>(Ah, Al, Wh, Wl, Gbuf, N, lda);

        amp_warp<<<BV / 8, 256>>>(Gbuf, T, Bw[l], Gw[l], Ew[l], outs[l]);
    }

    gmax_v4<<<dim3(BATCH, 16), 64>>>(xB, Part);
    mlp_kernel<<<BATCH, 512>>>(Part, w1, c1, w2, c2, w3, c3, out);
}

// round 11
// speedup vs baseline: 3.5358x; 1.0120x over previous
#include <cuda_runtime.h>
#include <cuda_bf16.h>
#include <cstdint>
#include <math.h>

// ---------------------------------------------------------------------------
// Problem constants
// ---------------------------------------------------------------------------
#define BATCH 4
#define NV    2048
#define BV    (BATCH * NV)      // 8192
#define NR    5
#define NA    8
#define RA    (NR * NA)         // 40
#define CIN   30
#define KDMAX 5120              // RA * 128
#define NMAX  2048              // NA * 256

// ---------------------------------------------------------------------------
// PTX helpers (portable: sm_80-class tensor core path, works on sm_103 target)
// ---------------------------------------------------------------------------
__device__ __forceinline__ uint32_t smem_u32(const void* p) {
    uint32_t a;
    asm("{ .reg .u64 t; cvta.to.shared.u64 t, %1; cvt.u32.u64 %0, t; }" : "=r"(a) : "l"(p));
    return a;
}
#define CP_ASYNC_CG(dst, src) \
    asm volatile("cp.async.cg.shared.global [%0], [%1], 16;" :: "r"(dst), "l"(src))
#define CP_COMMIT() asm volatile("cp.async.commit_group;" ::: "memory")
#define CP_WAIT(n)  asm volatile("cp.async.wait_group %0;" :: "n"(n) : "memory")

#define LDSM_X4(r0, r1, r2, r3, addr) \
    asm volatile("ldmatrix.sync.aligned.m8n8.x4.shared.b16 {%0,%1,%2,%3}, [%4];" \
                 : "=r"(r0), "=r"(r1), "=r"(r2), "=r"(r3) : "r"(addr))

#define MMA_BF16(d, a0, a1, a2, a3, b0, b1) \
    asm volatile("mma.sync.aligned.m16n8k16.row.col.f32.bf16.bf16.f32 " \
                 "{%0,%1,%2,%3}, {%4,%5,%6,%7}, {%8,%9}, {%0,%1,%2,%3};" \
                 : "+f"((d)[0]), "+f"((d)[1]), "+f"((d)[2]), "+f"((d)[3]) \
                 : "r"(a0), "r"(a1), "r"(a2), "r"(a3), "r"(b0), "r"(b1))

// ---------------------------------------------------------------------------
// Scratch (device globals; no runtime allocation allowed)
// ---------------------------------------------------------------------------
__device__ __align__(256) float          g_xA[BV * 128];
__device__ __align__(256) float          g_xB[BV * 256];
__device__ __align__(256) __nv_bfloat16  g_Ah[(long)BV * KDMAX];
__device__ __align__(256) __nv_bfloat16  g_Al[(long)BV * KDMAX];
__device__ __align__(256) __nv_bfloat16  g_Wh[(long)NMAX * KDMAX];
__device__ __align__(256) __nv_bfloat16  g_Wl[(long)NMAX * KDMAX];
__device__ __align__(256) float          g_G[(long)BV * NMAX];
__device__ __align__(256) float          g_part[BATCH * 16 * 256];

// ---------------------------------------------------------------------------
// Normalization constants (Keras adaption stats)
// ---------------------------------------------------------------------------
__constant__ float c_mean[CIN] = {
    -3.7189561e-06f, 0.000286194f, 0.0020740835f, 6.5275993f, -0.0052857199f,
    10.554636f, 0.057773598f, 13.915789f, 0.060970016f, 16.840271f,
    0.0570364f, 19.415283f, 0.044104282f, 21.721455f, 0.11490919f,
    23.64683f, 0.099816084f, 25.365578f, 0.01769533f, 26.861437f,
    0.054662503f, 28.197876f, -0.0024771576f, 29.295244f, 0.039666731f,
    30.319246f, 0.0088442909f, 31.160933f, -0.026727753f, 31.874565f};
__constant__ float c_var[CIN] = {
    3.3091978e-06f, 0.00016750646f, 0.80988622f, 85135.219f, 1.5621265f,
    222580.2f, 8.812871f, 386912.78f, 10.180468f, 566622.44f,
    9.8600769f, 753158.06f, 7.8372045f, 942701.62f, 30.926426f,
    1117233.0f, 25.045353f, 1285543.9f, 6.3646226f, 1441639.1f,
    12.326629f, 1588653.4f, 6.9686499f, 1714707.9f, 10.755516f,
    1836677.8f, 8.416419f, 1940088.8f, 10.344138f, 2029969.6f};

__device__ __forceinline__ float elu1(float x) { return x > 0.0f ? x : expm1f(x); }

// Fast branchless ELU: exact for x>=0, __expf-based for x<0 (~1e-7 abs error)
__device__ __forceinline__ float elu_fast(float x) {
    float e = __expf(fminf(x, 0.0f)) - 1.0f;
    return x > 0.0f ? x : e;
}

// ---------------------------------------------------------------------------
// 1) Input normalization -> padded [BV, 32] (channels 30,31 = 0)
// ---------------------------------------------------------------------------
__global__ void norm_kernel(const float* __restrict__ sig, float* __restrict__ x0) {
    int i = blockIdx.x * blockDim.x + threadIdx.x;
    if (i < BV * 32) {
        int c = i & 31, bv = i >> 5;
        x0[i] = (c < CIN) ? (sig[bv * CIN + c] - c_mean[c]) * rsqrtf(c_var[c]) : 0.0f;
    }
}

// ---------------------------------------------------------------------------
// 2) Barycentric gather + interp -> split bf16 hi/lo A. One block per vertex,
//    idx/w staged in smem, float4 gathers, packed 8-B bf16x4 stores.
// ---------------------------------------------------------------------------
__global__ void __launch_bounds__(128) interp_v4(
    const float* __restrict__ x, int Cp, int c4log, int lda,
    const int* __restrict__ bc_idx, const float* __restrict__ bc_w,
    __nv_bfloat16* __restrict__ Ah, __nv_bfloat16* __restrict__ Al)
{
    __shared__ int   sidx[RA * 3];
    __shared__ float sw[RA * 3];
    const int bv  = blockIdx.x;
    const int tid = threadIdx.x;
    if (tid < RA * 3) {
        sidx[tid] = bc_idx[bv * RA * 3 + tid];
        sw[tid]   = bc_w[bv * RA * 3 + tid];
    }
    __syncthreads();
    const int C4 = 1 << c4log;          // Cp/4
    const int total = RA << c4log;
    const long xbase = (long)(bv >> 11) << 11;   // b*NV
    for (int u = tid; u < total; u += 128) {
        int ra = u >> c4log;
        int c4 = u & (C4 - 1);
        int i0 = sidx[ra * 3], i1 = sidx[ra * 3 + 1], i2 = sidx[ra * 3 + 2];
        float w0 = sw[ra * 3], w1 = sw[ra * 3 + 1], w2 = sw[ra * 3 + 2];
        const float4* r0 = (const float4*)(x + (xbase + i0) * Cp);
        const float4* r1 = (const float4*)(x + (xbase + i1) * Cp);
        const float4* r2 = (const float4*)(x + (xbase + i2) * Cp);
        float4 a = r0[c4], b = r1[c4], c = r2[c4];
        float4 v;
        v.x = w0 * a.x + w1 * b.x + w2 * c.x;
        v.y = w0 * a.y + w1 * b.y + w2 * c.y;
        v.z = w0 * a.z + w1 * b.z + w2 * c.z;
        v.w = w0 * a.w + w1 * b.w + w2 * c.w;
        __nv_bfloat16 hx = __float2bfloat16(v.x), hy = __float2bfloat16(v.y);
        __nv_bfloat16 hz = __float2bfloat16(v.z), hw = __float2bfloat16(v.w);
        union { __nv_bfloat162 b2[2]; uint2 u2; } hi, lo;
        hi.b2[0] = __halves2bfloat162(hx, hy);
        hi.b2[1] = __halves2bfloat162(hz, hw);
        lo.b2[0] = __halves2bfloat162(__float2bfloat16(v.x - __bfloat162float(hx)),
                                      __float2bfloat16(v.y - __bfloat162float(hy)));
        lo.b2[1] = __halves2bfloat162(__float2bfloat16(v.z - __bfloat162float(hz)),
                                      __float2bfloat16(v.w - __bfloat162float(hw)));
        long off = (long)bv * lda + ra * Cp + c4 * 4;
        *(uint2*)(Ah + off) = hi.u2;
        *(uint2*)(Al + off) = lo.u2;
    }
}

// ---------------------------------------------------------------------------
// 3a) Rotated kernel -> transposed split bf16 B (vector, C multiple of 4):
//     Wt[n][ra*C + c] = K[r, (a - n/T) mod 8, n%T, c]
// ---------------------------------------------------------------------------
__global__ void __launch_bounds__(128) rot_v4(
    const float* __restrict__ Kw, int Tlog, int C, int c4log, int lda,
    __nv_bfloat16* __restrict__ Wh, __nv_bfloat16* __restrict__ Wl)
{
    const int n = blockIdx.x;
    const int t = n & ((1 << Tlog) - 1);
    const int o = n >> Tlog;
    const int C4 = 1 << c4log;
    const int total = RA << c4log;
    for (int u = threadIdx.x; u < total; u += 128) {
        int ra = u >> c4log, c4 = u & (C4 - 1);
        int a = ra & 7, r = ra >> 3;
        int as = (a - o + 8) & 7;
        const float4* src = (const float4*)(Kw + (long)((((r << 3) + as) << Tlog) + t) * C);
        float4 v = src[c4];
        __nv_bfloat16 hx = __float2bfloat16(v.x), hy = __float2bfloat16(v.y);
        __nv_bfloat16 hz = __float2bfloat16(v.z), hw = __float2bfloat16(v.w);
        union { __nv_bfloat162 b2[2]; uint2 u2; } hi, lo;
        hi.b2[0] = __halves2bfloat162(hx, hy);
        hi.b2[1] = __halves2bfloat162(hz, hw);
        lo.b2[0] = __halves2bfloat162(__float2bfloat16(v.x - __bfloat162float(hx)),
                                      __float2bfloat16(v.y - __bfloat162float(hy)));
        lo.b2[1] = __halves2bfloat162(__float2bfloat16(v.z - __bfloat162float(hz)),
                                      __float2bfloat16(v.w - __bfloat162float(hw)));
        long off = (long)n * lda + ra * C + c4 * 4;
        *(uint2*)(Wh + off) = hi.u2;
        *(uint2*)(Wl + off) = lo.u2;
    }
}

// ---------------------------------------------------------------------------
// 3b) Rotated kernel, scalar variant for layer 0 (C=30 real, Cp=32 padded)
// ---------------------------------------------------------------------------
__global__ void __launch_bounds__(128) rot_sc(
    const float* __restrict__ Kw, int Tlog, int lda,
    __nv_bfloat16* __restrict__ Wh, __nv_bfloat16* __restrict__ Wl)
{
    const int n = blockIdx.x;
    const int t = n & ((1 << Tlog) - 1);
    const int o = n >> Tlog;
    const int total = RA * 32;
    for (int u = threadIdx.x; u < total; u += 128) {
        int ra = u >> 5, c = u & 31;
        int a = ra & 7, r = ra >> 3;
        int as = (a - o + 8) & 7;
        float v = (c < CIN) ? Kw[(long)((((r << 3) + as) << Tlog) + t) * CIN + c] : 0.0f;
        __nv_bfloat16 h = __float2bfloat16(v);
        long off = (long)n * lda + ra * 32 + c;
        Wh[off] = h;
        Wl[off] = __float2bfloat16(v - __bfloat162float(h));
    }
}

// ---------------------------------------------------------------------------
// 4) Tensor-core GEMM via mma.sync (bf16, fp32 accum), error-compensated:
//    acc += Ah*Wh + Al*Wh + Ah*Wl  (R8-passing version, unchanged)
// ---------------------------------------------------------------------------
#define MAT_BYTES 8192                  // 128 rows * 64 B
#define STAGE_BYTES (4 * MAT_BYTES)     // Ah, Al, Wh, Wl
#define GEMM_SMEM (2 * STAGE_BYTES)     // 65536

__device__ __forceinline__ uint32_t swz(int row, int ch) {
    return (uint32_t)(row * 64 + ((ch ^ ((row >> 1) & 3)) << 4));
}

__global__ void __launch_bounds__(256, 2) gemm_mma(
    const __nv_bfloat16* __restrict__ Ah, const __nv_bfloat16* __restrict__ Al,
    const __nv_bfloat16* __restrict__ Wh, const __nv_bfloat16* __restrict__ Wl,
    float* __restrict__ Cout, int N, int ldk)
{
    extern __shared__ char smem[];
    const uint32_t sb = smem_u32(smem);
    const int tid = threadIdx.x, lane = tid & 31, wid = tid >> 5;
    const int wm = (wid & 3) * 32;
    const int wn = (wid >> 2) * 64;
    const long m0 = (long)blockIdx.y * 128;
    const long n0 = (long)blockIdx.x * 128;

    const int lr  = (tid >> 2) & 63;
    const int lch = tid & 3;
    const __nv_bfloat16* gbase[4] = {Ah, Al, Wh, Wl};

    float acc[2][8][4];
#pragma unroll
    for (int i = 0; i < 2; i++)
#pragma unroll
        for (int j = 0; j < 8; j++)
#pragma unroll
            for (int q = 0; q < 4; q++) acc[i][j][q] = 0.0f;

    const int nk = ldk >> 5;

    const int a_row = wm + ((lane >> 3) & 1) * 8 + (lane & 7);
    const int a_chs = lane >> 4;
    const int b_row = wn + ((lane >> 4) & 1) * 8 + (lane & 7);
    const int b_chs = (lane >> 3) & 1;

    {
        const long k0 = 0;
#pragma unroll
        for (int it = 0; it < 8; it++) {
            int mat = it >> 1;
            int row = lr + (it & 1) * 64;
            long grow = (mat < 2 ? m0 : n0) + row;
            const __nv_bfloat16* g = gbase[mat] + grow * ldk + k0 + lch * 8;
            uint32_t dst = sb + mat * MAT_BYTES + swz(row, lch);
            CP_ASYNC_CG(dst, g);
        }
        CP_COMMIT();
    }

    for (int j = 0; j < nk; j++) {
        int s = j & 1;
        if (j + 1 < nk) {
            const long k0 = (long)(j + 1) << 5;
            uint32_t stg = sb + ((j + 1) & 1) * STAGE_BYTES;
#pragma unroll
            for (int it = 0; it < 8; it++) {
                int mat = it >> 1;
                int row = lr + (it & 1) * 64;
                long grow = (mat < 2 ? m0 : n0) + row;
                const __nv_bfloat16* g = gbase[mat] + grow * ldk + k0 + lch * 8;
                uint32_t dst = stg + mat * MAT_BYTES + swz(row, lch);
                CP_ASYNC_CG(dst, g);
            }
            CP_COMMIT();
            CP_WAIT(1);
        } else {
            CP_WAIT(0);
        }
        __syncthreads();

        const uint32_t base = sb + s * STAGE_BYTES;
#pragma unroll
        for (int kg = 0; kg < 2; kg++) {
            uint32_t ah[2][4], al[2][4];
#pragma unroll
            for (int mg = 0; mg < 2; mg++) {
                int row = a_row + mg * 16;
                int ch = 2 * kg + a_chs;
                uint32_t addr = base + swz(row, ch);
                LDSM_X4(ah[mg][0], ah[mg][1], ah[mg][2], ah[mg][3], addr);
                LDSM_X4(al[mg][0], al[mg][1], al[mg][2], al[mg][3], addr + MAT_BYTES);
            }
#pragma unroll
            for (int p = 0; p < 4; p++) {
                int row = b_row + p * 16;
                int ch = 2 * kg + b_chs;
                uint32_t baddr = base + 2 * MAT_BYTES + swz(row, ch);
                uint32_t bh0, bh1, bh2, bh3, bl0, bl1, bl2, bl3;
                LDSM_X4(bh0, bh1, bh2, bh3, baddr);
                LDSM_X4(bl0, bl1, bl2, bl3, baddr + MAT_BYTES);
#pragma unroll
                for (int mg = 0; mg < 2; mg++) {
                    MMA_BF16(acc[mg][2 * p],     ah[mg][0], ah[mg][1], ah[mg][2], ah[mg][3], bh0, bh1);
                    MMA_BF16(acc[mg][2 * p],     al[mg][0], al[mg][1], al[mg][2], al[mg][3], bh0, bh1);
                    MMA_BF16(acc[mg][2 * p],     ah[mg][0], ah[mg][1], ah[mg][2], ah[mg][3], bl0, bl1);
                    MMA_BF16(acc[mg][2 * p + 1], ah[mg][0], ah[mg][1], ah[mg][2], ah[mg][3], bh2, bh3);
                    MMA_BF16(acc[mg][2 * p + 1], al[mg][0], al[mg][1], al[mg][2], al[mg][3], bh2, bh3);
                    MMA_BF16(acc[mg][2 * p + 1], ah[mg][0], ah[mg][1], ah[mg][2], ah[mg][3], bl2, bl3);
                }
            }
        }
        __syncthreads();
    }

    const int erow = lane >> 2;
    const int ecol = 2 * (lane & 3);
#pragma unroll
    for (int mg = 0; mg < 2; mg++) {
#pragma unroll
        for (int g = 0; g < 8; g++) {
            long row = m0 + wm + mg * 16 + erow;
            long col = n0 + wn + g * 8 + ecol;
            float2 v0 = make_float2(acc[mg][g][0], acc[mg][g][1]);
            float2 v1 = make_float2(acc[mg][g][2], acc[mg][g][3]);
            *(float2*)(Cout + row * N + col) = v0;
            *(float2*)(Cout + (row + 8) * N + col) = v1;
        }
    }
}

// ---------------------------------------------------------------------------
// 5) Epilogue: bias + ELU, angular max pooling, BN — one warp per vertex.
//    Uses fast branchless ELU (MUFU ex2) instead of expm1f polynomial.
// ---------------------------------------------------------------------------
__global__ void __launch_bounds__(256) amp_warp(
    const float* __restrict__ G, int T,
    const float* __restrict__ bias, const float* __restrict__ gamma,
    const float* __restrict__ beta, float* __restrict__ xnext)
{
    const int gw   = (blockIdx.x * blockDim.x + threadIdx.x) >> 5;  // vertex
    const int lane = threadIdx.x & 31;
    if (gw >= BV) return;
    const int C4T = T >> 2;
    const int nj  = C4T >> 5;   // 1 (T=128) or 2 (T=256)
    const float4* row = (const float4*)(G + (long)gw * NA * T);
    const float4* b4  = (const float4*)bias;
    int besto = 0; float bestn = -1.0f;
#pragma unroll
    for (int o = 0; o < NA; o++) {
        float s = 0.0f;
        for (int j = 0; j < nj; j++) {
            int c4 = lane + j * 32;
            float4 v = row[o * C4T + c4];
            float4 bb = b4[c4];
            float e0 = elu_fast(v.x + bb.x), e1 = elu_fast(v.y + bb.y);
            float e2 = elu_fast(v.z + bb.z), e3 = elu_fast(v.w + bb.w);
            s += e0 * e0 + e1 * e1 + e2 * e2 + e3 * e3;
        }
        s += __shfl_xor_sync(0xffffffffu, s, 16);
        s += __shfl_xor_sync(0xffffffffu, s, 8);
        s += __shfl_xor_sync(0xffffffffu, s, 4);
        s += __shfl_xor_sync(0xffffffffu, s, 2);
        s += __shfl_xor_sync(0xffffffffu, s, 1);
        if (s > bestn) { bestn = s; besto = o; }
    }
    const float scale = rsqrtf(1.0f + 1e-3f);
    const float4* g4  = (const float4*)gamma;
    const float4* be4 = (const float4*)beta;
    float4* out4 = (float4*)(xnext + (long)gw * T);
    for (int j = 0; j < nj; j++) {
        int c4 = lane + j * 32;
        float4 v = row[besto * C4T + c4];
        float4 bb = b4[c4], gg = g4[c4], ee = be4[c4];
        float4 r;
        r.x = gg.x * elu1(v.x + bb.x) * scale + ee.x;
        r.y = gg.y * elu1(v.y + bb.y) * scale + ee.y;
        r.z = gg.z * elu1(v.z + bb.z) * scale + ee.z;
        r.w = gg.w * elu1(v.w + bb.w) * scale + ee.w;
        out4[c4] = r;
    }
}

// ---------------------------------------------------------------------------
// 6) Global max pool partials (float4)
// ---------------------------------------------------------------------------
__global__ void gmax_v4(const float* __restrict__ x, float* __restrict__ part) {
    int b = blockIdx.x, ch = blockIdx.y, c4 = threadIdx.x;   // 64 threads
    const float4* x4 = (const float4*)x + (long)(b * NV + ch * 128) * 64;
    float4 m = make_float4(-3.4e38f, -3.4e38f, -3.4e38f, -3.4e38f);
    for (int v = 0; v < 128; v++) {
        float4 val = x4[(long)v * 64 + c4];
        m.x = fmaxf(m.x, val.x); m.y = fmaxf(m.y, val.y);
        m.z = fmaxf(m.z, val.z); m.w = fmaxf(m.w, val.w);
    }
    ((float4*)part)[(b * 16 + ch) * 64 + c4] = m;
}

// ---------------------------------------------------------------------------
// 7) MLP head
// ---------------------------------------------------------------------------
__global__ void mlp_kernel(const float* __restrict__ part,
                           const float* __restrict__ w1, const float* __restrict__ c1,
                           const float* __restrict__ w2, const float* __restrict__ c2,
                           const float* __restrict__ w3, const float* __restrict__ c3,
                           float* __restrict__ out) {
    int b = blockIdx.x, tid = threadIdx.x;  // 512 threads
    __shared__ float h0[256], h1[512], h2[256];
    if (tid < 256) {
        float m = -3.4e38f;
        for (int ch = 0; ch < 16; ch++)
            m = fmaxf(m, part[(b * 16 + ch) * 256 + tid]);
        h0[tid] = m;
    }
    __syncthreads();
    {
        float acc = c1[tid];
        for (int k = 0; k < 256; k++) acc += h0[k] * w1[k * 512 + tid];
        h1[tid] = elu1(acc);
    }
    __syncthreads();
    if (tid < 256) {
        float acc = c2[tid];
        for (int k = 0; k < 512; k++) acc += h1[k] * w2[k * 256 + tid];
        h2[tid] = elu1(acc);
    }
    __syncthreads();
    if (tid < 40) {
        float acc = c3[tid];
        for (int k = 0; k < 256; k++) acc += h2[k] * w3[k * 40 + tid];
        out[b * 40 + tid] = acc;
    }
}

// ---------------------------------------------------------------------------
// Launch
// ---------------------------------------------------------------------------
extern "C" void kernel_launch(void* const* d_in, const int* in_sizes, int n_in,
                              void* d_out, int out_size) {
    const float* signal = (const float*)d_in[0];
    const int*   bc_idx = (const int*)  d_in[1];
    const float* bc_w   = (const float*)d_in[2];
    const float* Kw[3]  = {(const float*)d_in[3],  (const float*)d_in[7],  (const float*)d_in[11]};
    const float* Bw[3]  = {(const float*)d_in[4],  (const float*)d_in[8],  (const float*)d_in[12]};
    const float* Gw[3]  = {(const float*)d_in[5],  (const float*)d_in[9],  (const float*)d_in[13]};
    const float* Ew[3]  = {(const float*)d_in[6],  (const float*)d_in[10], (const float*)d_in[14]};
    const float* w1 = (const float*)d_in[15]; const float* c1 = (const float*)d_in[16];
    const float* w2 = (const float*)d_in[17]; const float* c2 = (const float*)d_in[18];
    const float* w3 = (const float*)d_in[19]; const float* c3 = (const float*)d_in[20];
    float* out = (float*)d_out;

    float *xA, *xB, *Gbuf, *Part;
    __nv_bfloat16 *Ah, *Al, *Wh, *Wl;
    cudaGetSymbolAddress((void**)&xA,   g_xA);
    cudaGetSymbolAddress((void**)&xB,   g_xB);
    cudaGetSymbolAddress((void**)&Ah,   g_Ah);
    cudaGetSymbolAddress((void**)&Al,   g_Al);
    cudaGetSymbolAddress((void**)&Wh,   g_Wh);
    cudaGetSymbolAddress((void**)&Wl,   g_Wl);
    cudaGetSymbolAddress((void**)&Gbuf, g_G);
    cudaGetSymbolAddress((void**)&Part, g_part);

    cudaFuncSetAttribute(gemm_mma, cudaFuncAttributeMaxDynamicSharedMemorySize, GEMM_SMEM);

    norm_kernel<<<(BV * 32 + 255) / 256, 256>>>(signal, xA);

    const int Cp[3]    = {32, 128, 128};   // padded channels
    const int c4log[3] = {3, 5, 5};
    const int Ts[3]    = {128, 128, 256};
    const int Tlog[3]  = {7, 7, 8};
    const int Kdp[3]   = {1280, 5120, 5120};
    float* ins[3]  = {xA, xB, xA};
    float* outs[3] = {xB, xA, xB};

    for (int l = 0; l < 3; l++) {
        int T = Ts[l], lda = Kdp[l];
        int N = NA * T;

        interp_v4<<<BV, 128>>>(ins[l], Cp[l], c4log[l], lda, bc_idx, bc_w, Ah, Al);

        if (l == 0)
            rot_sc<<<N, 128>>>(Kw[l], Tlog[l], lda, Wh, Wl);
        else
            rot_v4<<<N, 128>>>(Kw[l], Tlog[l], Cp[l], c4log[l], lda, Wh, Wl);

        dim3 grid(N / 128, BV / 128);
        gemm_mma<<<grid, 256, GEMM_SMEM>>>(Ah, Al, Wh, Wl, Gbuf, N, lda);

        amp_warp<<<BV / 8, 256>>>(Gbuf, T, Bw[l], Gw[l], Ew[l], outs[l]);
    }

    gmax_v4<<<dim3(BATCH, 16), 64>>>(xB, Part);
    mlp_kernel<<<BATCH, 512>>>(Part, w1, c1, w2, c2, w3, c3, out);
}

// round 13
// speedup vs baseline: 3.5688x; 1.0093x over previous
#include <cuda_runtime.h>
#include <cuda_bf16.h>
#include <cstdint>
#include <math.h>

// ---------------------------------------------------------------------------
// Problem constants
// ---------------------------------------------------------------------------
#define BATCH 4
#define NV    2048
#define BV    (BATCH * NV)      // 8192
#define NR    5
#define NA    8
#define RA    (NR * NA)         // 40
#define CIN   30
#define KDMAX 5120              // RA * 128
#define NMAX  2048              // NA * 256

// ---------------------------------------------------------------------------
// PTX helpers (portable: sm_80-class tensor core path, works on sm_103 target)
// ---------------------------------------------------------------------------
__device__ __forceinline__ uint32_t smem_u32(const void* p) {
    uint32_t a;
    asm("{ .reg .u64 t; cvta.to.shared.u64 t, %1; cvt.u32.u64 %0, t; }" : "=r"(a) : "l"(p));
    return a;
}
#define CP_ASYNC_CG(dst, src) \
    asm volatile("cp.async.cg.shared.global [%0], [%1], 16;" :: "r"(dst), "l"(src))
#define CP_COMMIT() asm volatile("cp.async.commit_group;" ::: "memory")
#define CP_WAIT(n)  asm volatile("cp.async.wait_group %0;" :: "n"(n) : "memory")

#define LDSM_X4(r0, r1, r2, r3, addr) \
    asm volatile("ldmatrix.sync.aligned.m8n8.x4.shared.b16 {%0,%1,%2,%3}, [%4];" \
                 : "=r"(r0), "=r"(r1), "=r"(r2), "=r"(r3) : "r"(addr))

#define MMA_BF16(d, a0, a1, a2, a3, b0, b1) \
    asm volatile("mma.sync.aligned.m16n8k16.row.col.f32.bf16.bf16.f32 " \
                 "{%0,%1,%2,%3}, {%4,%5,%6,%7}, {%8,%9}, {%0,%1,%2,%3};" \
                 : "+f"((d)[0]), "+f"((d)[1]), "+f"((d)[2]), "+f"((d)[3]) \
                 : "r"(a0), "r"(a1), "r"(a2), "r"(a3), "r"(b0), "r"(b1))

// ---------------------------------------------------------------------------
// Scratch (device globals; no runtime allocation allowed)
// ---------------------------------------------------------------------------
__device__ __align__(256) float          g_xA[BV * 128];
__device__ __align__(256) float          g_xB[BV * 256];
__device__ __align__(256) __nv_bfloat16  g_Ah[(long)BV * KDMAX];
__device__ __align__(256) __nv_bfloat16  g_Al[(long)BV * KDMAX];
__device__ __align__(256) __nv_bfloat16  g_Wh[(long)NMAX * KDMAX];
__device__ __align__(256) __nv_bfloat16  g_Wl[(long)NMAX * KDMAX];
__device__ __align__(256) float          g_G[(long)BV * NMAX];
__device__ __align__(256) float          g_part[BATCH * 16 * 256];

// ---------------------------------------------------------------------------
// Normalization constants (Keras adaption stats)
// ---------------------------------------------------------------------------
__constant__ float c_mean[CIN] = {
    -3.7189561e-06f, 0.000286194f, 0.0020740835f, 6.5275993f, -0.0052857199f,
    10.554636f, 0.057773598f, 13.915789f, 0.060970016f, 16.840271f,
    0.0570364f, 19.415283f, 0.044104282f, 21.721455f, 0.11490919f,
    23.64683f, 0.099816084f, 25.365578f, 0.01769533f, 26.861437f,
    0.054662503f, 28.197876f, -0.0024771576f, 29.295244f, 0.039666731f,
    30.319246f, 0.0088442909f, 31.160933f, -0.026727753f, 31.874565f};
__constant__ float c_var[CIN] = {
    3.3091978e-06f, 0.00016750646f, 0.80988622f, 85135.219f, 1.5621265f,
    222580.2f, 8.812871f, 386912.78f, 10.180468f, 566622.44f,
    9.8600769f, 753158.06f, 7.8372045f, 942701.62f, 30.926426f,
    1117233.0f, 25.045353f, 1285543.9f, 6.3646226f, 1441639.1f,
    12.326629f, 1588653.4f, 6.9686499f, 1714707.9f, 10.755516f,
    1836677.8f, 8.416419f, 1940088.8f, 10.344138f, 2029969.6f};

__device__ __forceinline__ float elu1(float x) { return x > 0.0f ? x : expm1f(x); }

// Fast branchless ELU: exact for x>=0, __expf-based for x<0 (~1e-7 abs error)
__device__ __forceinline__ float elu_fast(float x) {
    float e = __expf(fminf(x, 0.0f)) - 1.0f;
    return x > 0.0f ? x : e;
}

// Split a float4 into hi/lo bf16x4 using packed cvt + bit-shift reconstruction.
__device__ __forceinline__ void bsplit4(const float4 v, uint2& hi, uint2& lo) {
    union { __nv_bfloat162 b; uint32_t u; } p0, p1, q0, q1;
    p0.b = __floats2bfloat162_rn(v.x, v.y);
    p1.b = __floats2bfloat162_rn(v.z, v.w);
    float fx = __uint_as_float(p0.u << 16);
    float fy = __uint_as_float(p0.u & 0xffff0000u);
    float fz = __uint_as_float(p1.u << 16);
    float fw = __uint_as_float(p1.u & 0xffff0000u);
    q0.b = __floats2bfloat162_rn(v.x - fx, v.y - fy);
    q1.b = __floats2bfloat162_rn(v.z - fz, v.w - fw);
    hi = make_uint2(p0.u, p1.u);
    lo = make_uint2(q0.u, q1.u);
}

// ---------------------------------------------------------------------------
// 1) Input normalization -> padded [BV, 32] (channels 30,31 = 0)
// ---------------------------------------------------------------------------
__global__ void norm_kernel(const float* __restrict__ sig, float* __restrict__ x0) {
    int i = blockIdx.x * blockDim.x + threadIdx.x;
    if (i < BV * 32) {
        int c = i & 31, bv = i >> 5;
        x0[i] = (c < CIN) ? (sig[bv * CIN + c] - c_mean[c]) * rsqrtf(c_var[c]) : 0.0f;
    }
}

// ---------------------------------------------------------------------------
// 2+3) Fused pre-GEMM producer: blocks [0, BV) do barycentric interp (A-side),
//      blocks [BV, BV+N) do kernel rotation expansion (W-side). Co-scheduling
//      hides the rot work under interp occupancy (no stream juggling needed).
// ---------------------------------------------------------------------------
__global__ void __launch_bounds__(128) fused_pre(
    const float* __restrict__ x, int Cp, int c4log, int lda,
    const int* __restrict__ bc_idx, const float* __restrict__ bc_w,
    __nv_bfloat16* __restrict__ Ah, __nv_bfloat16* __restrict__ Al,
    const float* __restrict__ Kw, int Tlog, int isL0,
    __nv_bfloat16* __restrict__ Wh, __nv_bfloat16* __restrict__ Wl)
{
    const int tid = threadIdx.x;
    if (blockIdx.x < BV) {
        // ------- interp part -------
        __shared__ int   sidx[RA * 3];
        __shared__ float sw[RA * 3];
        const int bv = blockIdx.x;
        if (tid < RA * 3) {
            sidx[tid] = bc_idx[bv * RA * 3 + tid];
            sw[tid]   = bc_w[bv * RA * 3 + tid];
        }
        __syncthreads();
        const int C4 = 1 << c4log;
        const int total = RA << c4log;
        const long xbase = (long)(bv >> 11) << 11;   // b*NV
        for (int u = tid; u < total; u += 128) {
            int ra = u >> c4log;
            int c4 = u & (C4 - 1);
            int i0 = sidx[ra * 3], i1 = sidx[ra * 3 + 1], i2 = sidx[ra * 3 + 2];
            float w0 = sw[ra * 3], w1 = sw[ra * 3 + 1], w2 = sw[ra * 3 + 2];
            const float4* r0 = (const float4*)(x + (xbase + i0) * Cp);
            const float4* r1 = (const float4*)(x + (xbase + i1) * Cp);
            const float4* r2 = (const float4*)(x + (xbase + i2) * Cp);
            float4 a = r0[c4], b = r1[c4], c = r2[c4];
            float4 v;
            v.x = w0 * a.x + w1 * b.x + w2 * c.x;
            v.y = w0 * a.y + w1 * b.y + w2 * c.y;
            v.z = w0 * a.z + w1 * b.z + w2 * c.z;
            v.w = w0 * a.w + w1 * b.w + w2 * c.w;
            uint2 hi, lo;
            bsplit4(v, hi, lo);
            long off = (long)bv * lda + ra * Cp + c4 * 4;
            *(uint2*)(Ah + off) = hi;
            *(uint2*)(Al + off) = lo;
        }
    } else {
        // ------- rot part -------
        const int n = blockIdx.x - BV;
        const int t = n & ((1 << Tlog) - 1);
        const int o = n >> Tlog;
        if (isL0) {
            // scalar: C=30 real, Cp=32 padded
            const int total = RA * 32;
            for (int u = tid; u < total; u += 128) {
                int ra = u >> 5, c = u & 31;
                int a = ra & 7, r = ra >> 3;
                int as = (a - o + 8) & 7;
                float v = (c < CIN) ? Kw[(long)((((r << 3) + as) << Tlog) + t) * CIN + c] : 0.0f;
                __nv_bfloat16 h = __float2bfloat16(v);
                long off = (long)n * lda + ra * 32 + c;
                Wh[off] = h;
                Wl[off] = __float2bfloat16(v - __bfloat162float(h));
            }
        } else {
            const int C4 = 1 << c4log;
            const int total = RA << c4log;
            for (int u = tid; u < total; u += 128) {
                int ra = u >> c4log, c4 = u & (C4 - 1);
                int a = ra & 7, r = ra >> 3;
                int as = (a - o + 8) & 7;
                const float4* src = (const float4*)(Kw + (long)((((r << 3) + as) << Tlog) + t) * Cp);
                float4 v = src[c4];
                uint2 hi, lo;
                bsplit4(v, hi, lo);
                long off = (long)n * lda + ra * Cp + c4 * 4;
                *(uint2*)(Wh + off) = hi;
                *(uint2*)(Wl + off) = lo;
            }
        }
    }
}

// ---------------------------------------------------------------------------
// 4) Tensor-core GEMM via mma.sync (bf16, fp32 accum), error-compensated:
//    acc += Ah*Wh + Al*Wh + Ah*Wl  (R8/R11-passing version, unchanged)
// ---------------------------------------------------------------------------
#define MAT_BYTES 8192                  // 128 rows * 64 B
#define STAGE_BYTES (4 * MAT_BYTES)     // Ah, Al, Wh, Wl
#define GEMM_SMEM (2 * STAGE_BYTES)     // 65536

__device__ __forceinline__ uint32_t swz(int row, int ch) {
    return (uint32_t)(row * 64 + ((ch ^ ((row >> 1) & 3)) << 4));
}

__global__ void __launch_bounds__(256, 2) gemm_mma(
    const __nv_bfloat16* __restrict__ Ah, const __nv_bfloat16* __restrict__ Al,
    const __nv_bfloat16* __restrict__ Wh, const __nv_bfloat16* __restrict__ Wl,
    float* __restrict__ Cout, int N, int ldk)
{
    extern __shared__ char smem[];
    const uint32_t sb = smem_u32(smem);
    const int tid = threadIdx.x, lane = tid & 31, wid = tid >> 5;
    const int wm = (wid & 3) * 32;
    const int wn = (wid >> 2) * 64;
    const long m0 = (long)blockIdx.y * 128;
    const long n0 = (long)blockIdx.x * 128;

    const int lr  = (tid >> 2) & 63;
    const int lch = tid & 3;
    const __nv_bfloat16* gbase[4] = {Ah, Al, Wh, Wl};

    float acc[2][8][4];
#pragma unroll
    for (int i = 0; i < 2; i++)
#pragma unroll
        for (int j = 0; j < 8; j++)
#pragma unroll
            for (int q = 0; q < 4; q++) acc[i][j][q] = 0.0f;

    const int nk = ldk >> 5;

    const int a_row = wm + ((lane >> 3) & 1) * 8 + (lane & 7);
    const int a_chs = lane >> 4;
    const int b_row = wn + ((lane >> 4) & 1) * 8 + (lane & 7);
    const int b_chs = (lane >> 3) & 1;

    {
        const long k0 = 0;
#pragma unroll
        for (int it = 0; it < 8; it++) {
            int mat = it >> 1;
            int row = lr + (it & 1) * 64;
            long grow = (mat < 2 ? m0 : n0) + row;
            const __nv_bfloat16* g = gbase[mat] + grow * ldk + k0 + lch * 8;
            uint32_t dst = sb + mat * MAT_BYTES + swz(row, lch);
            CP_ASYNC_CG(dst, g);
        }
        CP_COMMIT();
    }

    for (int j = 0; j < nk; j++) {
        int s = j & 1;
        if (j + 1 < nk) {
            const long k0 = (long)(j + 1) << 5;
            uint32_t stg = sb + ((j + 1) & 1) * STAGE_BYTES;
#pragma unroll
            for (int it = 0; it < 8; it++) {
                int mat = it >> 1;
                int row = lr + (it & 1) * 64;
                long grow = (mat < 2 ? m0 : n0) + row;
                const __nv_bfloat16* g = gbase[mat] + grow * ldk + k0 + lch * 8;
                uint32_t dst = stg + mat * MAT_BYTES + swz(row, lch);
                CP_ASYNC_CG(dst, g);
            }
            CP_COMMIT();
            CP_WAIT(1);
        } else {
            CP_WAIT(0);
        }
        __syncthreads();

        const uint32_t base = sb + s * STAGE_BYTES;
#pragma unroll
        for (int kg = 0; kg < 2; kg++) {
            uint32_t ah[2][4], al[2][4];
#pragma unroll
            for (int mg = 0; mg < 2; mg++) {
                int row = a_row + mg * 16;
                int ch = 2 * kg + a_chs;
                uint32_t addr = base + swz(row, ch);
                LDSM_X4(ah[mg][0], ah[mg][1], ah[mg][2], ah[mg][3], addr);
                LDSM_X4(al[mg][0], al[mg][1], al[mg][2], al[mg][3], addr + MAT_BYTES);
            }
#pragma unroll
            for (int p = 0; p < 4; p++) {
                int row = b_row + p * 16;
                int ch = 2 * kg + b_chs;
                uint32_t baddr = base + 2 * MAT_BYTES + swz(row, ch);
                uint32_t bh0, bh1, bh2, bh3, bl0, bl1, bl2, bl3;
                LDSM_X4(bh0, bh1, bh2, bh3, baddr);
                LDSM_X4(bl0, bl1, bl2, bl3, baddr + MAT_BYTES);
#pragma unroll
                for (int mg = 0; mg < 2; mg++) {
                    MMA_BF16(acc[mg][2 * p],     ah[mg][0], ah[mg][1], ah[mg][2], ah[mg][3], bh0, bh1);
                    MMA_BF16(acc[mg][2 * p],     al[mg][0], al[mg][1], al[mg][2], al[mg][3], bh0, bh1);
                    MMA_BF16(acc[mg][2 * p],     ah[mg][0], ah[mg][1], ah[mg][2], ah[mg][3], bl0, bl1);
                    MMA_BF16(acc[mg][2 * p + 1], ah[mg][0], ah[mg][1], ah[mg][2], ah[mg][3], bh2, bh3);
                    MMA_BF16(acc[mg][2 * p + 1], al[mg][0], al[mg][1], al[mg][2], al[mg][3], bh2, bh3);
                    MMA_BF16(acc[mg][2 * p + 1], ah[mg][0], ah[mg][1], ah[mg][2], ah[mg][3], bl2, bl3);
                }
            }
        }
        __syncthreads();
    }

    const int erow = lane >> 2;
    const int ecol = 2 * (lane & 3);
#pragma unroll
    for (int mg = 0; mg < 2; mg++) {
#pragma unroll
        for (int g = 0; g < 8; g++) {
            long row = m0 + wm + mg * 16 + erow;
            long col = n0 + wn + g * 8 + ecol;
            float2 v0 = make_float2(acc[mg][g][0], acc[mg][g][1]);
            float2 v1 = make_float2(acc[mg][g][2], acc[mg][g][3]);
            *(float2*)(Cout + row * N + col) = v0;
            *(float2*)(Cout + (row + 8) * N + col) = v1;
        }
    }
}

// ---------------------------------------------------------------------------
// 5) Epilogue: bias + ELU, angular max pooling, BN — one warp per vertex
// ---------------------------------------------------------------------------
__global__ void __launch_bounds__(256) amp_warp(
    const float* __restrict__ G, int T,
    const float* __restrict__ bias, const float* __restrict__ gamma,
    const float* __restrict__ beta, float* __restrict__ xnext)
{
    const int gw   = (blockIdx.x * blockDim.x + threadIdx.x) >> 5;  // vertex
    const int lane = threadIdx.x & 31;
    if (gw >= BV) return;
    const int C4T = T >> 2;
    const int nj  = C4T >> 5;   // 1 (T=128) or 2 (T=256)
    const float4* row = (const float4*)(G + (long)gw * NA * T);
    const float4* b4  = (const float4*)bias;
    int besto = 0; float bestn = -1.0f;
#pragma unroll
    for (int o = 0; o < NA; o++) {
        float s = 0.0f;
        for (int j = 0; j < nj; j++) {
            int c4 = lane + j * 32;
            float4 v = row[o * C4T + c4];
            float4 bb = b4[c4];
            float e0 = elu_fast(v.x + bb.x), e1 = elu_fast(v.y + bb.y);
            float e2 = elu_fast(v.z + bb.z), e3 = elu_fast(v.w + bb.w);
            s += e0 * e0 + e1 * e1 + e2 * e2 + e3 * e3;
        }
        s += __shfl_xor_sync(0xffffffffu, s, 16);
        s += __shfl_xor_sync(0xffffffffu, s, 8);
        s += __shfl_xor_sync(0xffffffffu, s, 4);
        s += __shfl_xor_sync(0xffffffffu, s, 2);
        s += __shfl_xor_sync(0xffffffffu, s, 1);
        if (s > bestn) { bestn = s; besto = o; }
    }
    const float scale = rsqrtf(1.0f + 1e-3f);
    const float4* g4  = (const float4*)gamma;
    const float4* be4 = (const float4*)beta;
    float4* out4 = (float4*)(xnext + (long)gw * T);
    for (int j = 0; j < nj; j++) {
        int c4 = lane + j * 32;
        float4 v = row[besto * C4T + c4];
        float4 bb = b4[c4], gg = g4[c4], ee = be4[c4];
        float4 r;
        r.x = gg.x * elu_fast(v.x + bb.x) * scale + ee.x;
        r.y = gg.y * elu_fast(v.y + bb.y) * scale + ee.y;
        r.z = gg.z * elu_fast(v.z + bb.z) * scale + ee.z;
        r.w = gg.w * elu_fast(v.w + bb.w) * scale + ee.w;
        out4[c4] = r;
    }
}

// ---------------------------------------------------------------------------
// 6) Global max pool partials (float4)
// ---------------------------------------------------------------------------
__global__ void gmax_v4(const float* __restrict__ x, float* __restrict__ part) {
    int b = blockIdx.x, ch = blockIdx.y, c4 = threadIdx.x;   // 64 threads
    const float4* x4 = (const float4*)x + (long)(b * NV + ch * 128) * 64;
    float4 m = make_float4(-3.4e38f, -3.4e38f, -3.4e38f, -3.4e38f);
    for (int v = 0; v < 128; v++) {
        float4 val = x4[(long)v * 64 + c4];
        m.x = fmaxf(m.x, val.x); m.y = fmaxf(m.y, val.y);
        m.z = fmaxf(m.z, val.z); m.w = fmaxf(m.w, val.w);
    }
    ((float4*)part)[(b * 16 + ch) * 64 + c4] = m;
}

// ---------------------------------------------------------------------------
// 7) MLP head
// ---------------------------------------------------------------------------
__global__ void mlp_kernel(const float* __restrict__ part,
                           const float* __restrict__ w1, const float* __restrict__ c1,
                           const float* __restrict__ w2, const float* __restrict__ c2,
                           const float* __restrict__ w3, const float* __restrict__ c3,
                           float* __restrict__ out) {
    int b = blockIdx.x, tid = threadIdx.x;  // 512 threads
    __shared__ float h0[256], h1[512], h2[256];
    if (tid < 256) {
        float m = -3.4e38f;
        for (int ch = 0; ch < 16; ch++)
            m = fmaxf(m, part[(b * 16 + ch) * 256 + tid]);
        h0[tid] = m;
    }
    __syncthreads();
    {
        float acc = c1[tid];
        for (int k = 0; k < 256; k++) acc += h0[k] * w1[k * 512 + tid];
        h1[tid] = elu1(acc);
    }
    __syncthreads();
    if (tid < 256) {
        float acc = c2[tid];
        for (int k = 0; k < 512; k++) acc += h1[k] * w2[k * 256 + tid];
        h2[tid] = elu1(acc);
    }
    __syncthreads();
    if (tid < 40) {
        float acc = c3[tid];
        for (int k = 0; k < 256; k++) acc += h2[k] * w3[k * 40 + tid];
        out[b * 40 + tid] = acc;
    }
}

// ---------------------------------------------------------------------------
// Launch
// ---------------------------------------------------------------------------
extern "C" void kernel_launch(void* const* d_in, const int* in_sizes, int n_in,
                              void* d_out, int out_size) {
    const float* signal = (const float*)d_in[0];
    const int*   bc_idx = (const int*)  d_in[1];
    const float* bc_w   = (const float*)d_in[2];
    const float* Kw[3]  = {(const float*)d_in[3],  (const float*)d_in[7],  (const float*)d_in[11]};
    const float* Bw[3]  = {(const float*)d_in[4],  (const float*)d_in[8],  (const float*)d_in[12]};
    const float* Gw[3]  = {(const float*)d_in[5],  (const float*)d_in[9],  (const float*)d_in[13]};
    const float* Ew[3]  = {(const float*)d_in[6],  (const float*)d_in[10], (const float*)d_in[14]};
    const float* w1 = (const float*)d_in[15]; const float* c1 = (const float*)d_in[16];
    const float* w2 = (const float*)d_in[17]; const float* c2 = (const float*)d_in[18];
    const float* w3 = (const float*)d_in[19]; const float* c3 = (const float*)d_in[20];
    float* out = (float*)d_out;

    float *xA, *xB, *Gbuf, *Part;
    __nv_bfloat16 *Ah, *Al, *Wh, *Wl;
    cudaGetSymbolAddress((void**)&xA,   g_xA);
    cudaGetSymbolAddress((void**)&xB,   g_xB);
    cudaGetSymbolAddress((void**)&Ah,   g_Ah);
    cudaGetSymbolAddress((void**)&Al,   g_Al);
    cudaGetSymbolAddress((void**)&Wh,   g_Wh);
    cudaGetSymbolAddress((void**)&Wl,   g_Wl);
    cudaGetSymbolAddress((void**)&Gbuf, g_G);
    cudaGetSymbolAddress((void**)&Part, g_part);

    cudaFuncSetAttribute(gemm_mma, cudaFuncAttributeMaxDynamicSharedMemorySize, GEMM_SMEM);

    norm_kernel<<<(BV * 32 + 255) / 256, 256>>>(signal, xA);

    const int Cp[3]    = {32, 128, 128};   // padded channels
    const int c4log[3] = {3, 5, 5};
    const int Ts[3]    = {128, 128, 256};
    const int Tlog[3]  = {7, 7, 8};
    const int Kdp[3]   = {1280, 5120, 5120};
    float* ins[3]  = {xA, xB, xA};
    float* outs[3] = {xB, xA, xB};

    for (int l = 0; l < 3; l++) {
        int T = Ts[l], lda = Kdp[l];
        int N = NA * T;

        fused_pre<<<BV + N, 128>>>(ins[l], Cp[l], c4log[l], lda, bc_idx, bc_w,
                                   Ah, Al, Kw[l], Tlog[l], l == 0 ? 1 : 0, Wh, Wl);

        dim3 grid(N / 128, BV / 128);
        gemm_mma<<<grid, 256, GEMM_SMEM>>>(Ah, Al, Wh, Wl, Gbuf, N, lda);

        amp_warp<<<BV / 8, 256>>>(Gbuf, T, Bw[l], Gw[l], Ew[l], outs[l]);
    }

    gmax_v4<<<dim3(BATCH, 16), 64>>>(xB, Part);
    mlp_kernel<<<BATCH, 512>>>(Part, w1, c1, w2, c2, w3, c3, out);
}

// round 14
// speedup vs baseline: 3.5744x; 1.0016x over previous
#include <cuda_runtime.h>
#include <cuda_bf16.h>
#include <cstdint>
#include <math.h>

// ---------------------------------------------------------------------------
// Problem constants
// ---------------------------------------------------------------------------
#define BATCH 4
#define NV    2048
#define BV    (BATCH * NV)      // 8192
#define NR    5
#define NA    8
#define RA    (NR * NA)         // 40
#define CIN   30
#define KDMAX 5120              // RA * 128
#define NMAX  2048              // NA * 256

// ---------------------------------------------------------------------------
// PTX helpers (portable: sm_80-class tensor core path, works on sm_103 target)
// ---------------------------------------------------------------------------
__device__ __forceinline__ uint32_t smem_u32(const void* p) {
    uint32_t a;
    asm("{ .reg .u64 t; cvta.to.shared.u64 t, %1; cvt.u32.u64 %0, t; }" : "=r"(a) : "l"(p));
    return a;
}
#define CP_ASYNC_CG(dst, src) \
    asm volatile("cp.async.cg.shared.global [%0], [%1], 16;" :: "r"(dst), "l"(src))
#define CP_COMMIT() asm volatile("cp.async.commit_group;" ::: "memory")
#define CP_WAIT(n)  asm volatile("cp.async.wait_group %0;" :: "n"(n) : "memory")

#define LDSM_X4(r0, r1, r2, r3, addr) \
    asm volatile("ldmatrix.sync.aligned.m8n8.x4.shared.b16 {%0,%1,%2,%3}, [%4];" \
                 : "=r"(r0), "=r"(r1), "=r"(r2), "=r"(r3) : "r"(addr))

#define MMA_BF16(d, a0, a1, a2, a3, b0, b1) \
    asm volatile("mma.sync.aligned.m16n8k16.row.col.f32.bf16.bf16.f32 " \
                 "{%0,%1,%2,%3}, {%4,%5,%6,%7}, {%8,%9}, {%0,%1,%2,%3};" \
                 : "+f"((d)[0]), "+f"((d)[1]), "+f"((d)[2]), "+f"((d)[3]) \
                 : "r"(a0), "r"(a1), "r"(a2), "r"(a3), "r"(b0), "r"(b1))

// ---------------------------------------------------------------------------
// Scratch (device globals; no runtime allocation allowed)
// ---------------------------------------------------------------------------
__device__ __align__(256) float          g_xA[BV * 128];
__device__ __align__(256) float          g_xB[BV * 256];
__device__ __align__(256) __nv_bfloat16  g_Ah[(long)BV * KDMAX];
__device__ __align__(256) __nv_bfloat16  g_Al[(long)BV * KDMAX];
__device__ __align__(256) __nv_bfloat16  g_Wh[(long)NMAX * KDMAX];
__device__ __align__(256) __nv_bfloat16  g_Wl[(long)NMAX * KDMAX];
__device__ __align__(256) float          g_G[(long)BV * NMAX];
__device__ __align__(256) float          g_part[BATCH * 16 * 256];

// ---------------------------------------------------------------------------
// Normalization constants (Keras adaption stats)
// ---------------------------------------------------------------------------
__constant__ float c_mean[CIN] = {
    -3.7189561e-06f, 0.000286194f, 0.0020740835f, 6.5275993f, -0.0052857199f,
    10.554636f, 0.057773598f, 13.915789f, 0.060970016f, 16.840271f,
    0.0570364f, 19.415283f, 0.044104282f, 21.721455f, 0.11490919f,
    23.64683f, 0.099816084f, 25.365578f, 0.01769533f, 26.861437f,
    0.054662503f, 28.197876f, -0.0024771576f, 29.295244f, 0.039666731f,
    30.319246f, 0.0088442909f, 31.160933f, -0.026727753f, 31.874565f};
__constant__ float c_var[CIN] = {
    3.3091978e-06f, 0.00016750646f, 0.80988622f, 85135.219f, 1.5621265f,
    222580.2f, 8.812871f, 386912.78f, 10.180468f, 566622.44f,
    9.8600769f, 753158.06f, 7.8372045f, 942701.62f, 30.926426f,
    1117233.0f, 25.045353f, 1285543.9f, 6.3646226f, 1441639.1f,
    12.326629f, 1588653.4f, 6.9686499f, 1714707.9f, 10.755516f,
    1836677.8f, 8.416419f, 1940088.8f, 10.344138f, 2029969.6f};

__device__ __forceinline__ float elu1(float x) { return x > 0.0f ? x : expm1f(x); }

// Fast branchless ELU: exact for x>=0, __expf-based for x<0 (~1e-7 abs error)
__device__ __forceinline__ float elu_fast(float x) {
    float e = __expf(fminf(x, 0.0f)) - 1.0f;
    return x > 0.0f ? x : e;
}

// Split a float4 into hi/lo bf16x4 using packed cvt + bit-shift reconstruction.
__device__ __forceinline__ void bsplit4(const float4 v, uint2& hi, uint2& lo) {
    union { __nv_bfloat162 b; uint32_t u; } p0, p1, q0, q1;
    p0.b = __floats2bfloat162_rn(v.x, v.y);
    p1.b = __floats2bfloat162_rn(v.z, v.w);
    float fx = __uint_as_float(p0.u << 16);
    float fy = __uint_as_float(p0.u & 0xffff0000u);
    float fz = __uint_as_float(p1.u << 16);
    float fw = __uint_as_float(p1.u & 0xffff0000u);
    q0.b = __floats2bfloat162_rn(v.x - fx, v.y - fy);
    q1.b = __floats2bfloat162_rn(v.z - fz, v.w - fw);
    hi = make_uint2(p0.u, p1.u);
    lo = make_uint2(q0.u, q1.u);
}

// Split two adjacent float4s (8 elements) -> 16B hi + 16B lo
__device__ __forceinline__ void bsplit8(const float4 va, const float4 vb,
                                        uint4& hi, uint4& lo) {
    uint2 h0, l0, h1, l1;
    bsplit4(va, h0, l0);
    bsplit4(vb, h1, l1);
    hi = make_uint4(h0.x, h0.y, h1.x, h1.y);
    lo = make_uint4(l0.x, l0.y, l1.x, l1.y);
}

// ---------------------------------------------------------------------------
// 1) Input normalization -> padded [BV, 32] (channels 30,31 = 0)
// ---------------------------------------------------------------------------
__global__ void norm_kernel(const float* __restrict__ sig, float* __restrict__ x0) {
    int i = blockIdx.x * blockDim.x + threadIdx.x;
    if (i < BV * 32) {
        int c = i & 31, bv = i >> 5;
        x0[i] = (c < CIN) ? (sig[bv * CIN + c] - c_mean[c]) * rsqrtf(c_var[c]) : 0.0f;
    }
}

// ---------------------------------------------------------------------------
// 2+3) Fused pre-GEMM producer, 8 elements per thread-iteration:
//      blocks [0, BV) interp (A-side), blocks [BV, BV+N) rotation (W-side).
//      c8log = log2(Cp/8). Numerically identical splits to prior rounds.
// ---------------------------------------------------------------------------
__global__ void __launch_bounds__(128) fused_pre(
    const float* __restrict__ x, int Cp, int c8log, int lda,
    const int* __restrict__ bc_idx, const float* __restrict__ bc_w,
    __nv_bfloat16* __restrict__ Ah, __nv_bfloat16* __restrict__ Al,
    const float* __restrict__ Kw, int Tlog, int isL0,
    __nv_bfloat16* __restrict__ Wh, __nv_bfloat16* __restrict__ Wl)
{
    const int tid = threadIdx.x;
    if (blockIdx.x < BV) {
        // ------- interp part -------
        __shared__ int   sidx[RA * 3];
        __shared__ float sw[RA * 3];
        const int bv = blockIdx.x;
        if (tid < RA * 3) {
            sidx[tid] = bc_idx[bv * RA * 3 + tid];
            sw[tid]   = bc_w[bv * RA * 3 + tid];
        }
        __syncthreads();
        const int C8 = 1 << c8log;          // Cp/8
        const int c8 = tid & (C8 - 1);
        const int ra0 = tid >> c8log;
        const int raStep = 128 >> c8log;
        const long xbase = (long)(bv >> 11) << 11;   // b*NV
        for (int ra = ra0; ra < RA; ra += raStep) {
            int i0 = sidx[ra * 3], i1 = sidx[ra * 3 + 1], i2 = sidx[ra * 3 + 2];
            float w0 = sw[ra * 3], w1 = sw[ra * 3 + 1], w2 = sw[ra * 3 + 2];
            const float4* r0 = (const float4*)(x + (xbase + i0) * Cp) + 2 * c8;
            const float4* r1 = (const float4*)(x + (xbase + i1) * Cp) + 2 * c8;
            const float4* r2 = (const float4*)(x + (xbase + i2) * Cp) + 2 * c8;
            float4 a0 = r0[0], a1 = r0[1];
            float4 b0 = r1[0], b1 = r1[1];
            float4 d0 = r2[0], d1 = r2[1];
            float4 va, vb;
            va.x = w0 * a0.x + w1 * b0.x + w2 * d0.x;
            va.y = w0 * a0.y + w1 * b0.y + w2 * d0.y;
            va.z = w0 * a0.z + w1 * b0.z + w2 * d0.z;
            va.w = w0 * a0.w + w1 * b0.w + w2 * d0.w;
            vb.x = w0 * a1.x + w1 * b1.x + w2 * d1.x;
            vb.y = w0 * a1.y + w1 * b1.y + w2 * d1.y;
            vb.z = w0 * a1.z + w1 * b1.z + w2 * d1.z;
            vb.w = w0 * a1.w + w1 * b1.w + w2 * d1.w;
            uint4 hi, lo;
            bsplit8(va, vb, hi, lo);
            long off = (long)bv * lda + ra * Cp + c8 * 8;
            *(uint4*)(Ah + off) = hi;
            *(uint4*)(Al + off) = lo;
        }
    } else {
        // ------- rot part -------
        const int n = blockIdx.x - BV;
        const int t = n & ((1 << Tlog) - 1);
        const int o = n >> Tlog;
        if (isL0) {
            // scalar: C=30 real, Cp=32 padded
            const int total = RA * 32;
            for (int u = tid; u < total; u += 128) {
                int ra = u >> 5, c = u & 31;
                int a = ra & 7, r = ra >> 3;
                int as = (a - o + 8) & 7;
                float v = (c < CIN) ? Kw[(long)((((r << 3) + as) << Tlog) + t) * CIN + c] : 0.0f;
                __nv_bfloat16 h = __float2bfloat16(v);
                long off = (long)n * lda + ra * 32 + c;
                Wh[off] = h;
                Wl[off] = __float2bfloat16(v - __bfloat162float(h));
            }
        } else {
            const int C8 = 1 << c8log;
            const int c8 = tid & (C8 - 1);
            const int ra0 = tid >> c8log;
            const int raStep = 128 >> c8log;
            for (int ra = ra0; ra < RA; ra += raStep) {
                int a = ra & 7, r = ra >> 3;
                int as = (a - o + 8) & 7;
                const float4* src = (const float4*)(Kw + (long)((((r << 3) + as) << Tlog) + t) * Cp) + 2 * c8;
                float4 va = src[0], vb = src[1];
                uint4 hi, lo;
                bsplit8(va, vb, hi, lo);
                long off = (long)n * lda + ra * Cp + c8 * 8;
                *(uint4*)(Wh + off) = hi;
                *(uint4*)(Wl + off) = lo;
            }
        }
    }
}

// ---------------------------------------------------------------------------
// 4) Tensor-core GEMM via mma.sync (bf16, fp32 accum), error-compensated:
//    acc += Ah*Wh + Al*Wh + Ah*Wl.  3-stage cp.async pipeline, 1 sync/iter.
// ---------------------------------------------------------------------------
#define MAT_BYTES 8192                  // 128 rows * 64 B
#define STAGE_BYTES (4 * MAT_BYTES)     // Ah, Al, Wh, Wl
#define GEMM_SMEM (3 * STAGE_BYTES)     // 98304 (3 stages)

__device__ __forceinline__ uint32_t swz(int row, int ch) {
    return (uint32_t)(row * 64 + ((ch ^ ((row >> 1) & 3)) << 4));
}

#define LOAD_STAGE(stg_off, kk) do {                                          \
    const long k0_ = (long)(kk) << 5;                                         \
    _Pragma("unroll")                                                         \
    for (int it = 0; it < 8; it++) {                                          \
        int mat = it >> 1;                                                    \
        int row = lr + (it & 1) * 64;                                         \
        long grow = (mat < 2 ? m0 : n0) + row;                                \
        const __nv_bfloat16* g = gbase[mat] + grow * ldk + k0_ + lch * 8;     \
        uint32_t dst = sb + (stg_off) + mat * MAT_BYTES + swz(row, lch);      \
        CP_ASYNC_CG(dst, g);                                                  \
    }                                                                         \
    CP_COMMIT();                                                              \
} while (0)

__global__ void __launch_bounds__(256, 2) gemm_mma(
    const __nv_bfloat16* __restrict__ Ah, const __nv_bfloat16* __restrict__ Al,
    const __nv_bfloat16* __restrict__ Wh, const __nv_bfloat16* __restrict__ Wl,
    float* __restrict__ Cout, int N, int ldk)
{
    extern __shared__ char smem[];
    const uint32_t sb = smem_u32(smem);
    const int tid = threadIdx.x, lane = tid & 31, wid = tid >> 5;
    const int wm = (wid & 3) * 32;
    const int wn = (wid >> 2) * 64;
    const long m0 = (long)blockIdx.y * 128;
    const long n0 = (long)blockIdx.x * 128;

    const int lr  = (tid >> 2) & 63;
    const int lch = tid & 3;
    const __nv_bfloat16* gbase[4] = {Ah, Al, Wh, Wl};

    float acc[2][8][4];
#pragma unroll
    for (int i = 0; i < 2; i++)
#pragma unroll
        for (int j = 0; j < 8; j++)
#pragma unroll
            for (int q = 0; q < 4; q++) acc[i][j][q] = 0.0f;

    const int nk = ldk >> 5;

    const int a_row = wm + ((lane >> 3) & 1) * 8 + (lane & 7);
    const int a_chs = lane >> 4;
    const int b_row = wn + ((lane >> 4) & 1) * 8 + (lane & 7);
    const int b_chs = (lane >> 3) & 1;

    // prologue: stages 0, 1 (nk >= 40 always)
    LOAD_STAGE(0, 0);
    LOAD_STAGE(STAGE_BYTES, 1);

    uint32_t sc_off = 0;                    // compute-stage offset
    uint32_t sl_off = 2 * STAGE_BYTES;      // load-stage offset (j+2)

    for (int j = 0; j < nk; j++) {
        if (j == nk - 1) { CP_WAIT(0); } else { CP_WAIT(1); }
        __syncthreads();
        if (j + 2 < nk) {
            LOAD_STAGE(sl_off, j + 2);
            sl_off += STAGE_BYTES;
            if (sl_off == 3 * STAGE_BYTES) sl_off = 0;
        }

        const uint32_t base = sb + sc_off;
        sc_off += STAGE_BYTES;
        if (sc_off == 3 * STAGE_BYTES) sc_off = 0;
#pragma unroll
        for (int kg = 0; kg < 2; kg++) {
            uint32_t ah[2][4], al[2][4];
#pragma unroll
            for (int mg = 0; mg < 2; mg++) {
                int row = a_row + mg * 16;
                int ch = 2 * kg + a_chs;
                uint32_t addr = base + swz(row, ch);
                LDSM_X4(ah[mg][0], ah[mg][1], ah[mg][2], ah[mg][3], addr);
                LDSM_X4(al[mg][0], al[mg][1], al[mg][2], al[mg][3], addr + MAT_BYTES);
            }
#pragma unroll
            for (int p = 0; p < 4; p++) {
                int row = b_row + p * 16;
                int ch = 2 * kg + b_chs;
                uint32_t baddr = base + 2 * MAT_BYTES + swz(row, ch);
                uint32_t bh0, bh1, bh2, bh3, bl0, bl1, bl2, bl3;
                LDSM_X4(bh0, bh1, bh2, bh3, baddr);
                LDSM_X4(bl0, bl1, bl2, bl3, baddr + MAT_BYTES);
#pragma unroll
                for (int mg = 0; mg < 2; mg++) {
                    MMA_BF16(acc[mg][2 * p],     ah[mg][0], ah[mg][1], ah[mg][2], ah[mg][3], bh0, bh1);
                    MMA_BF16(acc[mg][2 * p],     al[mg][0], al[mg][1], al[mg][2], al[mg][3], bh0, bh1);
                    MMA_BF16(acc[mg][2 * p],     ah[mg][0], ah[mg][1], ah[mg][2], ah[mg][3], bl0, bl1);
                    MMA_BF16(acc[mg][2 * p + 1], ah[mg][0], ah[mg][1], ah[mg][2], ah[mg][3], bh2, bh3);
                    MMA_BF16(acc[mg][2 * p + 1], al[mg][0], al[mg][1], al[mg][2], al[mg][3], bh2, bh3);
                    MMA_BF16(acc[mg][2 * p + 1], ah[mg][0], ah[mg][1], ah[mg][2], ah[mg][3], bl2, bl3);
                }
            }
        }
    }

    const int erow = lane >> 2;
    const int ecol = 2 * (lane & 3);
#pragma unroll
    for (int mg = 0; mg < 2; mg++) {
#pragma unroll
        for (int g = 0; g < 8; g++) {
            long row = m0 + wm + mg * 16 + erow;
            long col = n0 + wn + g * 8 + ecol;
            float2 v0 = make_float2(acc[mg][g][0], acc[mg][g][1]);
            float2 v1 = make_float2(acc[mg][g][2], acc[mg][g][3]);
            *(float2*)(Cout + row * N + col) = v0;
            *(float2*)(Cout + (row + 8) * N + col) = v1;
        }
    }
}

// ---------------------------------------------------------------------------
// 5) Epilogue: bias + ELU, angular max pooling, BN — one warp per vertex
// ---------------------------------------------------------------------------
__global__ void __launch_bounds__(256) amp_warp(
    const float* __restrict__ G, int T,
    const float* __restrict__ bias, const float* __restrict__ gamma,
    const float* __restrict__ beta, float* __restrict__ xnext)
{
    const int gw   = (blockIdx.x * blockDim.x + threadIdx.x) >> 5;  // vertex
    const int lane = threadIdx.x & 31;
    if (gw >= BV) return;
    const int C4T = T >> 2;
    const int nj  = C4T >> 5;   // 1 (T=128) or 2 (T=256)
    const float4* row = (const float4*)(G + (long)gw * NA * T);
    const float4* b4  = (const float4*)bias;
    int besto = 0; float bestn = -1.0f;
#pragma unroll
    for (int o = 0; o < NA; o++) {
        float s = 0.0f;
        for (int j = 0; j < nj; j++) {
            int c4 = lane + j * 32;
            float4 v = row[o * C4T + c4];
            float4 bb = b4[c4];
            float e0 = elu_fast(v.x + bb.x), e1 = elu_fast(v.y + bb.y);
            float e2 = elu_fast(v.z + bb.z), e3 = elu_fast(v.w + bb.w);
            s += e0 * e0 + e1 * e1 + e2 * e2 + e3 * e3;
        }
        s += __shfl_xor_sync(0xffffffffu, s, 16);
        s += __shfl_xor_sync(0xffffffffu, s, 8);
        s += __shfl_xor_sync(0xffffffffu, s, 4);
        s += __shfl_xor_sync(0xffffffffu, s, 2);
        s += __shfl_xor_sync(0xffffffffu, s, 1);
        if (s > bestn) { bestn = s; besto = o; }
    }
    const float scale = rsqrtf(1.0f + 1e-3f);
    const float4* g4  = (const float4*)gamma;
    const float4* be4 = (const float4*)beta;
    float4* out4 = (float4*)(xnext + (long)gw * T);
    for (int j = 0; j < nj; j++) {
        int c4 = lane + j * 32;
        float4 v = row[besto * C4T + c4];
        float4 bb = b4[c4], gg = g4[c4], ee = be4[c4];
        float4 r;
        r.x = gg.x * elu_fast(v.x + bb.x) * scale + ee.x;
        r.y = gg.y * elu_fast(v.y + bb.y) * scale + ee.y;
        r.z = gg.z * elu_fast(v.z + bb.z) * scale + ee.z;
        r.w = gg.w * elu_fast(v.w + bb.w) * scale + ee.w;
        out4[c4] = r;
    }
}

// ---------------------------------------------------------------------------
// 6) Global max pool partials (float4)
// ---------------------------------------------------------------------------
__global__ void gmax_v4(const float* __restrict__ x, float* __restrict__ part) {
    int b = blockIdx.x, ch = blockIdx.y, c4 = threadIdx.x;   // 64 threads
    const float4* x4 = (const float4*)x + (long)(b * NV + ch * 128) * 64;
    float4 m = make_float4(-3.4e38f, -3.4e38f, -3.4e38f, -3.4e38f);
    for (int v = 0; v < 128; v++) {
        float4 val = x4[(long)v * 64 + c4];
        m.x = fmaxf(m.x, val.x); m.y = fmaxf(m.y, val.y);
        m.z = fmaxf(m.z, val.z); m.w = fmaxf(m.w, val.w);
    }
    ((float4*)part)[(b * 16 + ch) * 64 + c4] = m;
}

// ---------------------------------------------------------------------------
// 7) MLP head
// ---------------------------------------------------------------------------
__global__ void mlp_kernel(const float* __restrict__ part,
                           const float* __restrict__ w1, const float* __restrict__ c1,
                           const float* __restrict__ w2, const float* __restrict__ c2,
                           const float* __restrict__ w3, const float* __restrict__ c3,
                           float* __restrict__ out) {
    int b = blockIdx.x, tid = threadIdx.x;  // 512 threads
    __shared__ float h0[256], h1[512], h2[256];
    if (tid < 256) {
        float m = -3.4e38f;
        for (int ch = 0; ch < 16; ch++)
            m = fmaxf(m, part[(b * 16 + ch) * 256 + tid]);
        h0[tid] = m;
    }
    __syncthreads();
    {
        float acc = c1[tid];
        for (int k = 0; k < 256; k++) acc += h0[k] * w1[k * 512 + tid];
        h1[tid] = elu1(acc);
    }
    __syncthreads();
    if (tid < 256) {
        float acc = c2[tid];
        for (int k = 0; k < 512; k++) acc += h1[k] * w2[k * 256 + tid];
        h2[tid] = elu1(acc);
    }
    __syncthreads();
    if (tid < 40) {
        float acc = c3[tid];
        for (int k = 0; k < 256; k++) acc += h2[k] * w3[k * 40 + tid];
        out[b * 40 + tid] = acc;
    }
}

// ---------------------------------------------------------------------------
// Launch
// ---------------------------------------------------------------------------
extern "C" void kernel_launch(void* const* d_in, const int* in_sizes, int n_in,
                              void* d_out, int out_size) {
    const float* signal = (const float*)d_in[0];
    const int*   bc_idx = (const int*)  d_in[1];
    const float* bc_w   = (const float*)d_in[2];
    const float* Kw[3]  = {(const float*)d_in[3],  (const float*)d_in[7],  (const float*)d_in[11]};
    const float* Bw[3]  = {(const float*)d_in[4],  (const float*)d_in[8],  (const float*)d_in[12]};
    const float* Gw[3]  = {(const float*)d_in[5],  (const float*)d_in[9],  (const float*)d_in[13]};
    const float* Ew[3]  = {(const float*)d_in[6],  (const float*)d_in[10], (const float*)d_in[14]};
    const float* w1 = (const float*)d_in[15]; const float* c1 = (const float*)d_in[16];
    const float* w2 = (const float*)d_in[17]; const float* c2 = (const float*)d_in[18];
    const float* w3 = (const float*)d_in[19]; const float* c3 = (const float*)d_in[20];
    float* out = (float*)d_out;

    float *xA, *xB, *Gbuf, *Part;
    __nv_bfloat16 *Ah, *Al, *Wh, *Wl;
    cudaGetSymbolAddress((void**)&xA,   g_xA);
    cudaGetSymbolAddress((void**)&xB,   g_xB);
    cudaGetSymbolAddress((void**)&Ah,   g_Ah);
    cudaGetSymbolAddress((void**)&Al,   g_Al);
    cudaGetSymbolAddress((void**)&Wh,   g_Wh);
    cudaGetSymbolAddress((void**)&Wl,   g_Wl);
    cudaGetSymbolAddress((void**)&Gbuf, g_G);
    cudaGetSymbolAddress((void**)&Part, g_part);

    cudaFuncSetAttribute(gemm_mma, cudaFuncAttributeMaxDynamicSharedMemorySize, GEMM_SMEM);

    norm_kernel<<<(BV * 32 + 255) / 256, 256>>>(signal, xA);

    const int Cp[3]    = {32, 128, 128};   // padded channels
    const int c8log[3] = {2, 4, 4};        // log2(Cp/8)
    const int Ts[3]    = {128, 128, 256};
    const int Tlog[3]  = {7, 7, 8};
    const int Kdp[3]   = {1280, 5120, 5120};
    float* ins[3]  = {xA, xB, xA};
    float* outs[3] = {xB, xA, xB};

    for (int l = 0; l < 3; l++) {
        int T = Ts[l], lda = Kdp[l];
        int N = NA * T;

        fused_pre<<<BV + N, 128>>>(ins[l], Cp[l], c8log[l], lda, bc_idx, bc_w,
                                   Ah, Al, Kw[l], Tlog[l], l == 0 ? 1 : 0, Wh, Wl);

        dim3 grid(N / 128, BV / 128);
        gemm_mma<<<grid, 256, GEMM_SMEM>>>(Ah, Al, Wh, Wl, Gbuf, N, lda);

        amp_warp<<<BV / 8, 256>>>(Gbuf, T, Bw[l], Gw[l], Ew[l], outs[l]);
    }

    gmax_v4<<<dim3(BATCH, 16), 64>>>(xB, Part);
    mlp_kernel<<<BATCH, 512>>>(Part, w1, c1, w2, c2, w3, c3, out);
}

// round 16
// speedup vs baseline: 9.7627x; 2.7313x over previous
#include <cuda_runtime.h>
#include <cuda_bf16.h>
#include <cstdint>
#include <math.h>

// ---------------------------------------------------------------------------
// Problem constants
// ---------------------------------------------------------------------------
#define BATCH 4
#define NV    2048
#define BV    (BATCH * NV)      // 8192
#define NR    5
#define NA    8
#define RA    (NR * NA)         // 40
#define CIN   30
#define KDMAX 5120
#define NMAX  2048

#define SQH 0.70710678118654752f   // sqrt(1/2)

// ---------------------------------------------------------------------------
// PTX helpers (portable mma.sync path)
// ---------------------------------------------------------------------------
__device__ __forceinline__ uint32_t smem_u32(const void* p) {
    uint32_t a;
    asm("{ .reg .u64 t; cvta.to.shared.u64 t, %1; cvt.u32.u64 %0, t; }" : "=r"(a) : "l"(p));
    return a;
}
#define CP_ASYNC_CG(dst, src) \
    asm volatile("cp.async.cg.shared.global [%0], [%1], 16;" :: "r"(dst), "l"(src))
#define CP_COMMIT() asm volatile("cp.async.commit_group;" ::: "memory")
#define CP_WAIT(n)  asm volatile("cp.async.wait_group %0;" :: "n"(n) : "memory")

#define LDSM_X4(r0, r1, r2, r3, addr) \
    asm volatile("ldmatrix.sync.aligned.m8n8.x4.shared.b16 {%0,%1,%2,%3}, [%4];" \
                 : "=r"(r0), "=r"(r1), "=r"(r2), "=r"(r3) : "r"(addr))

#define MMA_BF16(d, a0, a1, a2, a3, b0, b1) \
    asm volatile("mma.sync.aligned.m16n8k16.row.col.f32.bf16.bf16.f32 " \
                 "{%0,%1,%2,%3}, {%4,%5,%6,%7}, {%8,%9}, {%0,%1,%2,%3};" \
                 : "+f"((d)[0]), "+f"((d)[1]), "+f"((d)[2]), "+f"((d)[3]) \
                 : "r"(a0), "r"(a1), "r"(a2), "r"(a3), "r"(b0), "r"(b1))

// ---------------------------------------------------------------------------
// Scratch
// ---------------------------------------------------------------------------
__device__ __align__(256) float          g_xA[BV * 128];
__device__ __align__(256) float          g_xB[BV * 256];
__device__ __align__(256) __nv_bfloat16  g_Ah[(long)BV * KDMAX];
__device__ __align__(256) __nv_bfloat16  g_Al[(long)BV * KDMAX];
__device__ __align__(256) __nv_bfloat16  g_Wh[(long)NMAX * KDMAX];
__device__ __align__(256) __nv_bfloat16  g_Wl[(long)NMAX * KDMAX];
__device__ __align__(256) float          g_G[(long)BV * NMAX];
__device__ __align__(256) float          g_part[BATCH * 16 * 256];

// ---------------------------------------------------------------------------
// Normalization constants
// ---------------------------------------------------------------------------
__constant__ float c_mean[CIN] = {
    -3.7189561e-06f, 0.000286194f, 0.0020740835f, 6.5275993f, -0.0052857199f,
    10.554636f, 0.057773598f, 13.915789f, 0.060970016f, 16.840271f,
    0.0570364f, 19.415283f, 0.044104282f, 21.721455f, 0.11490919f,
    23.64683f, 0.099816084f, 25.365578f, 0.01769533f, 26.861437f,
    0.054662503f, 28.197876f, -0.0024771576f, 29.295244f, 0.039666731f,
    30.319246f, 0.0088442909f, 31.160933f, -0.026727753f, 31.874565f};
__constant__ float c_var[CIN] = {
    3.3091978e-06f, 0.00016750646f, 0.80988622f, 85135.219f, 1.5621265f,
    222580.2f, 8.812871f, 386912.78f, 10.180468f, 566622.44f,
    9.8600769f, 753158.06f, 7.8372045f, 942701.62f, 30.926426f,
    1117233.0f, 25.045353f, 1285543.9f, 6.3646226f, 1441639.1f,
    12.326629f, 1588653.4f, 6.9686499f, 1714707.9f, 10.755516f,
    1836677.8f, 8.416419f, 1940088.8f, 10.344138f, 2029969.6f};

// IDFT-8 reconstruction: g[o] = sum_j cM[o][j] * comp[j],
// comps = (Re0, Re4, Re1, Im1, Re2, Im2, Re3, Im3). Verified on delta/shift.
#define S2C 0.17677669529663689f   // 0.25 * sqrt(1/2)
__constant__ float cM[8][8] = {
    {0.125f,  0.125f,  0.25f,  0.f,    0.25f,  0.f,    0.25f,  0.f  },
    {0.125f, -0.125f,  S2C,   -S2C,    0.f,   -0.25f, -S2C,   -S2C },
    {0.125f,  0.125f,  0.f,   -0.25f, -0.25f,  0.f,    0.f,    0.25f},
    {0.125f, -0.125f, -S2C,   -S2C,    0.f,    0.25f,  S2C,   -S2C },
    {0.125f,  0.125f, -0.25f,  0.f,    0.25f,  0.f,   -0.25f,  0.f  },
    {0.125f, -0.125f, -S2C,    S2C,    0.f,   -0.25f,  S2C,    S2C },
    {0.125f,  0.125f,  0.f,    0.25f, -0.25f,  0.f,    0.f,   -0.25f},
    {0.125f, -0.125f,  S2C,    S2C,    0.f,    0.25f, -S2C,    S2C }};

__device__ __forceinline__ float elu1(float x) { return x > 0.0f ? x : expm1f(x); }
__device__ __forceinline__ float elu_fast(float x) {
    float e = __expf(fminf(x, 0.0f)) - 1.0f;
    return x > 0.0f ? x : e;
}

// Forward rFFT8: x[8] -> comps (Re0,Re4,Re1,Im1,Re2,Im2,Re3,Im3)
__device__ __forceinline__ void dft8(const float* x, float* o) {
    float u04 = x[0] - x[4], e26 = x[2] - x[6];
    float p = x[1] - x[3] - x[5] + x[7];
    float q = x[1] + x[3] - x[5] - x[7];
    o[0] = x[0] + x[1] + x[2] + x[3] + x[4] + x[5] + x[6] + x[7];
    o[1] = x[0] - x[1] + x[2] - x[3] + x[4] - x[5] + x[6] - x[7];
    o[2] = u04 + SQH * p;
    o[3] = -(SQH * q + e26);
    o[4] = x[0] - x[2] + x[4] - x[6];
    o[5] = -(x[1] - x[3] + x[5] - x[7]);
    o[6] = u04 - SQH * p;
    o[7] = -SQH * q + e26;
}

// Split a float4 into hi/lo bf16x4 via packed cvt + bit-shift reconstruction.
__device__ __forceinline__ void bsplit4(const float4 v, uint2& hi, uint2& lo) {
    union { __nv_bfloat162 b; uint32_t u; } p0, p1, q0, q1;
    p0.b = __floats2bfloat162_rn(v.x, v.y);
    p1.b = __floats2bfloat162_rn(v.z, v.w);
    float fx = __uint_as_float(p0.u << 16);
    float fy = __uint_as_float(p0.u & 0xffff0000u);
    float fz = __uint_as_float(p1.u << 16);
    float fw = __uint_as_float(p1.u & 0xffff0000u);
    q0.b = __floats2bfloat162_rn(v.x - fx, v.y - fy);
    q1.b = __floats2bfloat162_rn(v.z - fz, v.w - fw);
    hi = make_uint2(p0.u, p1.u);
    lo = make_uint2(q0.u, q1.u);
}
__device__ __forceinline__ void bsplit8(const float4 va, const float4 vb,
                                        uint4& hi, uint4& lo) {
    uint2 h0, l0, h1, l1;
    bsplit4(va, h0, l0);
    bsplit4(vb, h1, l1);
    hi = make_uint4(h0.x, h0.y, h1.x, h1.y);
    lo = make_uint4(l0.x, l0.y, l1.x, l1.y);
}

// ---------------------------------------------------------------------------
// 1) Input normalization -> padded [BV, 32]
// ---------------------------------------------------------------------------
__global__ void norm_kernel(const float* __restrict__ sig, float* __restrict__ x0) {
    int i = blockIdx.x * blockDim.x + threadIdx.x;
    if (i < BV * 32) {
        int c = i & 31, bv = i >> 5;
        x0[i] = (c < CIN) ? (sig[bv * CIN + c] - c_mean[c]) * rsqrtf(c_var[c]) : 0.0f;
    }
}

// ---------------------------------------------------------------------------
// 2+3) Fused producer in frequency domain.
//  A-side blocks [0,BV): per vertex, per (r, c8): gather all 8 angles,
//   interp, rFFT8, split -> 8 k-segments: k = seg*kq + r*Cp + c.
//  W-side blocks [BV, BV+T): per t: DFT of K over 'a', packed rows:
//   row t:    seg0 = Re0       row T+t: seg1 = Re4
//   row 2T+t: seg2=Re1 seg3=Im1   row 3T+t: seg2=-Im1 seg3=Re1
//   row 4T+t: seg4=Re2 seg5=Im2   row 5T+t: seg4=-Im2 seg5=Re2
//   row 6T+t: seg6=Re3 seg7=Im3   row 7T+t: seg6=-Im3 seg7=Re3
// ---------------------------------------------------------------------------
__global__ void __launch_bounds__(128) fused_pre(
    const float* __restrict__ x, int Cp, int c8log, int lda, int kq,
    const int* __restrict__ bc_idx, const float* __restrict__ bc_w,
    __nv_bfloat16* __restrict__ Ah, __nv_bfloat16* __restrict__ Al,
    const float* __restrict__ Kw, int Tlog, int T, int isL0,
    __nv_bfloat16* __restrict__ Wh, __nv_bfloat16* __restrict__ Wl)
{
    const int tid = threadIdx.x;
    if (blockIdx.x < BV) {
        // ---------------- interp + DFT (A-side) ----------------
        __shared__ int   sidx[RA * 3];
        __shared__ float sw[RA * 3];
        const int bv = blockIdx.x;
        if (tid < RA * 3) {
            sidx[tid] = bc_idx[bv * RA * 3 + tid];
            sw[tid]   = bc_w[bv * RA * 3 + tid];
        }
        __syncthreads();
        const int C8 = 1 << c8log;
        const int items = NR << c8log;       // 5 * Cp/8
        if (tid >= items) return;
        const int c8 = tid & (C8 - 1);
        const int r  = tid >> c8log;
        const long xbase = (long)(bv >> 11) << 11;

        float X[8][8];
#pragma unroll
        for (int a = 0; a < 8; a++) {
            int ra = r * 8 + a;
            int i0 = sidx[ra * 3], i1 = sidx[ra * 3 + 1], i2 = sidx[ra * 3 + 2];
            float w0 = sw[ra * 3], w1 = sw[ra * 3 + 1], w2 = sw[ra * 3 + 2];
            const float4* r0 = (const float4*)(x + (xbase + i0) * Cp) + 2 * c8;
            const float4* r1 = (const float4*)(x + (xbase + i1) * Cp) + 2 * c8;
            const float4* r2 = (const float4*)(x + (xbase + i2) * Cp) + 2 * c8;
            float4 a0 = r0[0], a1 = r0[1];
            float4 b0 = r1[0], b1 = r1[1];
            float4 d0 = r2[0], d1 = r2[1];
            X[a][0] = w0 * a0.x + w1 * b0.x + w2 * d0.x;
            X[a][1] = w0 * a0.y + w1 * b0.y + w2 * d0.y;
            X[a][2] = w0 * a0.z + w1 * b0.z + w2 * d0.z;
            X[a][3] = w0 * a0.w + w1 * b0.w + w2 * d0.w;
            X[a][4] = w0 * a1.x + w1 * b1.x + w2 * d1.x;
            X[a][5] = w0 * a1.y + w1 * b1.y + w2 * d1.y;
            X[a][6] = w0 * a1.z + w1 * b1.z + w2 * d1.z;
            X[a][7] = w0 * a1.w + w1 * b1.w + w2 * d1.w;
        }
#pragma unroll
        for (int j = 0; j < 8; j++) {
            float xx[8], oo[8];
#pragma unroll
            for (int a = 0; a < 8; a++) xx[a] = X[a][j];
            dft8(xx, oo);
#pragma unroll
            for (int a = 0; a < 8; a++) X[a][j] = oo[a];
        }
        const long base = (long)bv * lda + r * Cp + c8 * 8;
#pragma unroll
        for (int seg = 0; seg < 8; seg++) {
            float4 va = make_float4(X[seg][0], X[seg][1], X[seg][2], X[seg][3]);
            float4 vb = make_float4(X[seg][4], X[seg][5], X[seg][6], X[seg][7]);
            uint4 hi, lo;
            bsplit8(va, vb, hi, lo);
            long off = base + (long)seg * kq;
            *(uint4*)(Ah + off) = hi;
            *(uint4*)(Al + off) = lo;
        }
    } else {
        // ---------------- W-side DFT + pack ----------------
        const int t = blockIdx.x - BV;     // [0, T)
        if (isL0) {
            // scalar path: real C=30, padded Cp=32
            for (int u = tid; u < NR * 32; u += 128) {
                int r = u >> 5, c = u & 31;
                float xx[8], oo[8];
#pragma unroll
                for (int a = 0; a < 8; a++)
                    xx[a] = (c < CIN) ? Kw[(long)(((r * 8 + a) << Tlog) + t) * CIN + c] : 0.0f;
                dft8(xx, oo);
                int base = r * 32 + c;
#define WSC(row, seg, val) do {                                             \
    float v_ = (val);                                                       \
    __nv_bfloat16 h_ = __float2bfloat16(v_);                                \
    long o_ = (long)(row) * lda + (seg) * kq + base;                        \
    Wh[o_] = h_;                                                            \
    Wl[o_] = __float2bfloat16(v_ - __bfloat162float(h_));                   \
} while (0)
                WSC(t,         0,  oo[0]);
                WSC(T + t,     1,  oo[1]);
                WSC(2*T + t,   2,  oo[2]); WSC(2*T + t, 3,  oo[3]);
                WSC(3*T + t,   2, -oo[3]); WSC(3*T + t, 3,  oo[2]);
                WSC(4*T + t,   4,  oo[4]); WSC(4*T + t, 5,  oo[5]);
                WSC(5*T + t,   4, -oo[5]); WSC(5*T + t, 5,  oo[4]);
                WSC(6*T + t,   6,  oo[6]); WSC(6*T + t, 7,  oo[7]);
                WSC(7*T + t,   6, -oo[7]); WSC(7*T + t, 7,  oo[6]);
#undef WSC
            }
        } else {
            const int C8 = 1 << c8log;
            const int items = NR << c8log;
            if (tid >= items) return;
            const int c8 = tid & (C8 - 1);
            const int r  = tid >> c8log;
            float X[8][8];
#pragma unroll
            for (int a = 0; a < 8; a++) {
                const float4* src = (const float4*)(Kw + (long)(((r * 8 + a) << Tlog) + t) * Cp) + 2 * c8;
                float4 v0 = src[0], v1 = src[1];
                X[a][0] = v0.x; X[a][1] = v0.y; X[a][2] = v0.z; X[a][3] = v0.w;
                X[a][4] = v1.x; X[a][5] = v1.y; X[a][6] = v1.z; X[a][7] = v1.w;
            }
#pragma unroll
            for (int j = 0; j < 8; j++) {
                float xx[8], oo[8];
#pragma unroll
                for (int a = 0; a < 8; a++) xx[a] = X[a][j];
                dft8(xx, oo);
#pragma unroll
                for (int a = 0; a < 8; a++) X[a][j] = oo[a];
            }
            const long cbase = r * Cp + c8 * 8;
#define WSEG(row, seg, sgn, comp) do {                                       \
    float4 va_ = make_float4(sgn X[comp][0], sgn X[comp][1],                 \
                             sgn X[comp][2], sgn X[comp][3]);                \
    float4 vb_ = make_float4(sgn X[comp][4], sgn X[comp][5],                 \
                             sgn X[comp][6], sgn X[comp][7]);                \
    uint4 hi_, lo_;                                                          \
    bsplit8(va_, vb_, hi_, lo_);                                             \
    long o_ = (long)(row) * lda + (long)(seg) * kq + cbase;                  \
    *(uint4*)(Wh + o_) = hi_;                                                \
    *(uint4*)(Wl + o_) = lo_;                                                \
} while (0)
            WSEG(t,        0, +, 0);
            WSEG(T + t,    1, +, 1);
            WSEG(2*T + t,  2, +, 2); WSEG(2*T + t, 3, +, 3);
            WSEG(3*T + t,  2, -, 3); WSEG(3*T + t, 3, +, 2);
            WSEG(4*T + t,  4, +, 4); WSEG(4*T + t, 5, +, 5);
            WSEG(5*T + t,  4, -, 5); WSEG(5*T + t, 5, +, 4);
            WSEG(6*T + t,  6, +, 6); WSEG(6*T + t, 7, +, 7);
            WSEG(7*T + t,  6, -, 7); WSEG(7*T + t, 7, +, 6);
#undef WSEG
        }
    }
}

// ---------------------------------------------------------------------------
// 4) GEMM (bf16 mma.sync, fp32 accum, 3-pass compensated), banded K:
//    n-tile block b = blockIdx.x >> ulog selects (koff, klen):
//    koff = {0,1,2,2,4,4,6,6}[b]*kq ; klen = (b<2) ? kq : 2*kq.
// ---------------------------------------------------------------------------
#define MAT_BYTES 8192
#define STAGE_BYTES (4 * MAT_BYTES)
#define GEMM_SMEM (3 * STAGE_BYTES)

__device__ __forceinline__ uint32_t swz(int row, int ch) {
    return (uint32_t)(row * 64 + ((ch ^ ((row >> 1) & 3)) << 4));
}

#define LOAD_STAGE(stg_off, kk) do {                                          \
    const long k0_ = (long)(kk) << 5;                                         \
    _Pragma("unroll")                                                         \
    for (int it = 0; it < 8; it++) {                                          \
        int mat = it >> 1;                                                    \
        int row = lr + (it & 1) * 64;                                         \
        long grow = (mat < 2 ? m0 : n0) + row;                                \
        const __nv_bfloat16* g = gbase[mat] + grow * ldk + k0_ + lch * 8;     \
        uint32_t dst = sb + (stg_off) + mat * MAT_BYTES + swz(row, lch);      \
        CP_ASYNC_CG(dst, g);                                                  \
    }                                                                         \
    CP_COMMIT();                                                              \
} while (0)

__global__ void __launch_bounds__(256, 2) gemm_mma(
    const __nv_bfloat16* __restrict__ Ah, const __nv_bfloat16* __restrict__ Al,
    const __nv_bfloat16* __restrict__ Wh, const __nv_bfloat16* __restrict__ Wl,
    float* __restrict__ Cout, int N, int ldk, int kq, int ulog)
{
    extern __shared__ char smem[];
    const uint32_t sb = smem_u32(smem);
    const int tid = threadIdx.x, lane = tid & 31, wid = tid >> 5;
    const int wm = (wid & 3) * 32;
    const int wn = (wid >> 2) * 64;
    const long m0 = (long)blockIdx.y * 128;
    const long n0 = (long)blockIdx.x * 128;

    // K band for this n-tile
    const int b = blockIdx.x >> ulog;
    const int kofft[8] = {0, 1, 2, 2, 4, 4, 6, 6};
    const int koff = kofft[b] * kq;
    const int klen = (b < 2) ? kq : 2 * kq;
    const int j0 = koff >> 5;
    const int j1 = j0 + (klen >> 5);

    const int lr  = (tid >> 2) & 63;
    const int lch = tid & 3;
    const __nv_bfloat16* gbase[4] = {Ah, Al, Wh, Wl};

    float acc[2][8][4];
#pragma unroll
    for (int i = 0; i < 2; i++)
#pragma unroll
        for (int j = 0; j < 8; j++)
#pragma unroll
            for (int q = 0; q < 4; q++) acc[i][j][q] = 0.0f;

    const int a_row = wm + ((lane >> 3) & 1) * 8 + (lane & 7);
    const int a_chs = lane >> 4;
    const int b_row = wn + ((lane >> 4) & 1) * 8 + (lane & 7);
    const int b_chs = (lane >> 3) & 1;

    LOAD_STAGE(0, j0);
    LOAD_STAGE(STAGE_BYTES, j0 + 1);

    uint32_t sc_off = 0;
    uint32_t sl_off = 2 * STAGE_BYTES;

    for (int j = j0; j < j1; j++) {
        if (j == j1 - 1) { CP_WAIT(0); } else { CP_WAIT(1); }
        __syncthreads();
        if (j + 2 < j1) {
            LOAD_STAGE(sl_off, j + 2);
            sl_off += STAGE_BYTES;
            if (sl_off == 3 * STAGE_BYTES) sl_off = 0;
        }

        const uint32_t base = sb + sc_off;
        sc_off += STAGE_BYTES;
        if (sc_off == 3 * STAGE_BYTES) sc_off = 0;
#pragma unroll
        for (int kg = 0; kg < 2; kg++) {
            uint32_t ah[2][4], al[2][4];
#pragma unroll
            for (int mg = 0; mg < 2; mg++) {
                int row = a_row + mg * 16;
                int ch = 2 * kg + a_chs;
                uint32_t addr = base + swz(row, ch);
                LDSM_X4(ah[mg][0], ah[mg][1], ah[mg][2], ah[mg][3], addr);
                LDSM_X4(al[mg][0], al[mg][1], al[mg][2], al[mg][3], addr + MAT_BYTES);
            }
#pragma unroll
            for (int p = 0; p < 4; p++) {
                int row = b_row + p * 16;
                int ch = 2 * kg + b_chs;
                uint32_t baddr = base + 2 * MAT_BYTES + swz(row, ch);
                uint32_t bh0, bh1, bh2, bh3, bl0, bl1, bl2, bl3;
                LDSM_X4(bh0, bh1, bh2, bh3, baddr);
                LDSM_X4(bl0, bl1, bl2, bl3, baddr + MAT_BYTES);
#pragma unroll
                for (int mg = 0; mg < 2; mg++) {
                    MMA_BF16(acc[mg][2 * p],     ah[mg][0], ah[mg][1], ah[mg][2], ah[mg][3], bh0, bh1);
                    MMA_BF16(acc[mg][2 * p],     al[mg][0], al[mg][1], al[mg][2], al[mg][3], bh0, bh1);
                    MMA_BF16(acc[mg][2 * p],     ah[mg][0], ah[mg][1], ah[mg][2], ah[mg][3], bl0, bl1);
                    MMA_BF16(acc[mg][2 * p + 1], ah[mg][0], ah[mg][1], ah[mg][2], ah[mg][3], bh2, bh3);
                    MMA_BF16(acc[mg][2 * p + 1], al[mg][0], al[mg][1], al[mg][2], al[mg][3], bh2, bh3);
                    MMA_BF16(acc[mg][2 * p + 1], ah[mg][0], ah[mg][1], ah[mg][2], ah[mg][3], bl2, bl3);
                }
            }
        }
    }

    const int erow = lane >> 2;
    const int ecol = 2 * (lane & 3);
#pragma unroll
    for (int mg = 0; mg < 2; mg++) {
#pragma unroll
        for (int g = 0; g < 8; g++) {
            long row = m0 + wm + mg * 16 + erow;
            long col = n0 + wn + g * 8 + ecol;
            float2 v0 = make_float2(acc[mg][g][0], acc[mg][g][1]);
            float2 v1 = make_float2(acc[mg][g][2], acc[mg][g][3]);
            *(float2*)(Cout + row * N + col) = v0;
            *(float2*)(Cout + (row + 8) * N + col) = v1;
        }
    }
}

// ---------------------------------------------------------------------------
// 5) Epilogue: IDFT-8 reconstruct rotations + bias + ELU + AMP + BN.
//    G row layout: 8 component blocks of T: (Re0,Re4,Re1,Im1,Re2,Im2,Re3,Im3)
// ---------------------------------------------------------------------------
__global__ void __launch_bounds__(256) amp_warp(
    const float* __restrict__ G, int T,
    const float* __restrict__ bias, const float* __restrict__ gamma,
    const float* __restrict__ beta, float* __restrict__ xnext)
{
    const int gw   = (blockIdx.x * blockDim.x + threadIdx.x) >> 5;  // vertex
    const int lane = threadIdx.x & 31;
    if (gw >= BV) return;
    const int C4T = T >> 2;
    const int nj  = C4T >> 5;
    const float4* base4 = (const float4*)(G + (long)gw * NA * T);
    const float4* b4    = (const float4*)bias;

    float4 vals[2][8];
    for (int jj = 0; jj < nj; jj++) {
        int c4 = lane + jj * 32;
#pragma unroll
        for (int k = 0; k < 8; k++)
            vals[jj][k] = base4[k * C4T + c4];
    }

    int besto = 0; float bestn = -1.0f;
#pragma unroll
    for (int o = 0; o < NA; o++) {
        float s = 0.0f;
        for (int jj = 0; jj < nj; jj++) {
            int c4 = lane + jj * 32;
            float4 v = make_float4(0.f, 0.f, 0.f, 0.f);
#pragma unroll
            for (int k = 0; k < 8; k++) {
                float m = cM[o][k];
                v.x += m * vals[jj][k].x;
                v.y += m * vals[jj][k].y;
                v.z += m * vals[jj][k].z;
                v.w += m * vals[jj][k].w;
            }
            float4 bb = b4[c4];
            float e0 = elu_fast(v.x + bb.x), e1 = elu_fast(v.y + bb.y);
            float e2 = elu_fast(v.z + bb.z), e3 = elu_fast(v.w + bb.w);
            s += e0 * e0 + e1 * e1 + e2 * e2 + e3 * e3;
        }
        s += __shfl_xor_sync(0xffffffffu, s, 16);
        s += __shfl_xor_sync(0xffffffffu, s, 8);
        s += __shfl_xor_sync(0xffffffffu, s, 4);
        s += __shfl_xor_sync(0xffffffffu, s, 2);
        s += __shfl_xor_sync(0xffffffffu, s, 1);
        if (s > bestn) { bestn = s; besto = o; }
    }
    const float scale = rsqrtf(1.0f + 1e-3f);
    const float4* g4  = (const float4*)gamma;
    const float4* be4 = (const float4*)beta;
    float4* out4 = (float4*)(xnext + (long)gw * T);
    for (int jj = 0; jj < nj; jj++) {
        int c4 = lane + jj * 32;
        float4 v = make_float4(0.f, 0.f, 0.f, 0.f);
#pragma unroll
        for (int k = 0; k < 8; k++) {
            float m = cM[besto][k];
            v.x += m * vals[jj][k].x;
            v.y += m * vals[jj][k].y;
            v.z += m * vals[jj][k].z;
            v.w += m * vals[jj][k].w;
        }
        float4 bb = b4[c4], gg = g4[c4], ee = be4[c4];
        float4 r;
        r.x = gg.x * elu_fast(v.x + bb.x) * scale + ee.x;
        r.y = gg.y * elu_fast(v.y + bb.y) * scale + ee.y;
        r.z = gg.z * elu_fast(v.z + bb.z) * scale + ee.z;
        r.w = gg.w * elu_fast(v.w + bb.w) * scale + ee.w;
        out4[c4] = r;
    }
}

// ---------------------------------------------------------------------------
// 6) Global max pool partials (float4)
// ---------------------------------------------------------------------------
__global__ void gmax_v4(const float* __restrict__ x, float* __restrict__ part) {
    int b = blockIdx.x, ch = blockIdx.y, c4 = threadIdx.x;   // 64 threads
    const float4* x4 = (const float4*)x + (long)(b * NV + ch * 128) * 64;
    float4 m = make_float4(-3.4e38f, -3.4e38f, -3.4e38f, -3.4e38f);
    for (int v = 0; v < 128; v++) {
        float4 val = x4[(long)v * 64 + c4];
        m.x = fmaxf(m.x, val.x); m.y = fmaxf(m.y, val.y);
        m.z = fmaxf(m.z, val.z); m.w = fmaxf(m.w, val.w);
    }
    ((float4*)part)[(b * 16 + ch) * 64 + c4] = m;
}

// ---------------------------------------------------------------------------
// 7) MLP head
// ---------------------------------------------------------------------------
__global__ void mlp_kernel(const float* __restrict__ part,
                           const float* __restrict__ w1, const float* __restrict__ c1,
                           const float* __restrict__ w2, const float* __restrict__ c2,
                           const float* __restrict__ w3, const float* __restrict__ c3,
                           float* __restrict__ out) {
    int b = blockIdx.x, tid = threadIdx.x;  // 512 threads
    __shared__ float h0[256], h1[512], h2[256];
    if (tid < 256) {
        float m = -3.4e38f;
        for (int ch = 0; ch < 16; ch++)
            m = fmaxf(m, part[(b * 16 + ch) * 256 + tid]);
        h0[tid] = m;
    }
    __syncthreads();
    {
        float acc = c1[tid];
        for (int k = 0; k < 256; k++) acc += h0[k] * w1[k * 512 + tid];
        h1[tid] = elu1(acc);
    }
    __syncthreads();
    if (tid < 256) {
        float acc = c2[tid];
        for (int k = 0; k < 512; k++) acc += h1[k] * w2[k * 256 + tid];
        h2[tid] = elu1(acc);
    }
    __syncthreads();
    if (tid < 40) {
        float acc = c3[tid];
        for (int k = 0; k < 256; k++) acc += h2[k] * w3[k * 40 + tid];
        out[b * 40 + tid] = acc;
    }
}

// ---------------------------------------------------------------------------
// Launch
// ---------------------------------------------------------------------------
extern "C" void kernel_launch(void* const* d_in, const int* in_sizes, int n_in,
                              void* d_out, int out_size) {
    const float* signal = (const float*)d_in[0];
    const int*   bc_idx = (const int*)  d_in[1];
    const float* bc_w   = (const float*)d_in[2];
    const float* Kw[3]  = {(const float*)d_in[3],  (const float*)d_in[7],  (const float*)d_in[11]};
    const float* Bw[3]  = {(const float*)d_in[4],  (const float*)d_in[8],  (const float*)d_in[12]};
    const float* Gw[3]  = {(const float*)d_in[5],  (const float*)d_in[9],  (const float*)d_in[13]};
    const float* Ew[3]  = {(const float*)d_in[6],  (const float*)d_in[10], (const float*)d_in[14]};
    const float* w1 = (const float*)d_in[15]; const float* c1 = (const float*)d_in[16];
    const float* w2 = (const float*)d_in[17]; const float* c2 = (const float*)d_in[18];
    const float* w3 = (const float*)d_in[19]; const float* c3 = (const float*)d_in[20];
    float* out = (float*)d_out;

    float *xA, *xB, *Gbuf, *Part;
    __nv_bfloat16 *Ah, *Al, *Wh, *Wl;
    cudaGetSymbolAddress((void**)&xA,   g_xA);
    cudaGetSymbolAddress((void**)&xB,   g_xB);
    cudaGetSymbolAddress((void**)&Ah,   g_Ah);
    cudaGetSymbolAddress((void**)&Al,   g_Al);
    cudaGetSymbolAddress((void**)&Wh,   g_Wh);
    cudaGetSymbolAddress((void**)&Wl,   g_Wl);
    cudaGetSymbolAddress((void**)&Gbuf, g_G);
    cudaGetSymbolAddress((void**)&Part, g_part);

    cudaFuncSetAttribute(gemm_mma, cudaFuncAttributeMaxDynamicSharedMemorySize, GEMM_SMEM);

    norm_kernel<<<(BV * 32 + 255) / 256, 256>>>(signal, xA);

    const int Cp[3]    = {32, 128, 128};
    const int c8log[3] = {2, 4, 4};
    const int Ts[3]    = {128, 128, 256};
    const int Tlog[3]  = {7, 7, 8};
    const int ulog3[3] = {0, 0, 1};
    float* ins[3]  = {xA, xB, xA};
    float* outs[3] = {xB, xA, xB};

    for (int l = 0; l < 3; l++) {
        int T = Ts[l];
        int kq = 5 * Cp[l];          // 160 / 640 / 640
        int lda = 8 * kq;            // 1280 / 5120 / 5120
        int N = NA * T;

        fused_pre<<<BV + T, 128>>>(ins[l], Cp[l], c8log[l], lda, kq, bc_idx, bc_w,
                                   Ah, Al, Kw[l], Tlog[l], T, l == 0 ? 1 : 0, Wh, Wl);

        dim3 grid(N / 128, BV / 128);
        gemm_mma<<<grid, 256, GEMM_SMEM>>>(Ah, Al, Wh, Wl, Gbuf, N, lda, kq, ulog3[l]);

        amp_warp<<<BV / 8, 256>>>(Gbuf, T, Bw[l], Gw[l], Ew[l], outs[l]);
    }

    gmax_v4<<<dim3(BATCH, 16), 64>>>(xB, Part);
    mlp_kernel<<<BATCH, 512>>>(Part, w1, c1, w2, c2, w3, c3, out);
}

// round 17
// speedup vs baseline: 9.9078x; 1.0149x over previous
#include <cuda_runtime.h>
#include <cuda_bf16.h>
#include <cstdint>
#include <math.h>

// ---------------------------------------------------------------------------
// Problem constants
// ---------------------------------------------------------------------------
#define BATCH 4
#define NV    2048
#define BV    (BATCH * NV)      // 8192
#define NR    5
#define NA    8
#define RA    (NR * NA)         // 40
#define CIN   30
#define KDMAX 5120
#define NMAX  2048

#define SQH 0.70710678118654752f   // sqrt(1/2)

// ---------------------------------------------------------------------------
// PTX helpers (portable mma.sync path)
// ---------------------------------------------------------------------------
__device__ __forceinline__ uint32_t smem_u32(const void* p) {
    uint32_t a;
    asm("{ .reg .u64 t; cvta.to.shared.u64 t, %1; cvt.u32.u64 %0, t; }" : "=r"(a) : "l"(p));
    return a;
}
#define CP_ASYNC_CG(dst, src) \
    asm volatile("cp.async.cg.shared.global [%0], [%1], 16;" :: "r"(dst), "l"(src))
#define CP_COMMIT() asm volatile("cp.async.commit_group;" ::: "memory")
#define CP_WAIT(n)  asm volatile("cp.async.wait_group %0;" :: "n"(n) : "memory")

#define LDSM_X4(r0, r1, r2, r3, addr) \
    asm volatile("ldmatrix.sync.aligned.m8n8.x4.shared.b16 {%0,%1,%2,%3}, [%4];" \
                 : "=r"(r0), "=r"(r1), "=r"(r2), "=r"(r3) : "r"(addr))

#define MMA_BF16(d, a0, a1, a2, a3, b0, b1) \
    asm volatile("mma.sync.aligned.m16n8k16.row.col.f32.bf16.bf16.f32 " \
                 "{%0,%1,%2,%3}, {%4,%5,%6,%7}, {%8,%9}, {%0,%1,%2,%3};" \
                 : "+f"((d)[0]), "+f"((d)[1]), "+f"((d)[2]), "+f"((d)[3]) \
                 : "r"(a0), "r"(a1), "r"(a2), "r"(a3), "r"(b0), "r"(b1))

// ---------------------------------------------------------------------------
// Scratch
// ---------------------------------------------------------------------------
__device__ __align__(256) float          g_xA[BV * 128];
__device__ __align__(256) float          g_xB[BV * 256];
__device__ __align__(256) __nv_bfloat16  g_Ah[(long)BV * KDMAX];
__device__ __align__(256) __nv_bfloat16  g_Al[(long)BV * KDMAX];
__device__ __align__(256) __nv_bfloat16  g_Wh[(long)NMAX * KDMAX];
__device__ __align__(256) __nv_bfloat16  g_Wl[(long)NMAX * KDMAX];
__device__ __align__(256) float          g_G[(long)BV * NMAX];
__device__ __align__(256) float          g_part[BATCH * 16 * 256];

// ---------------------------------------------------------------------------
// Normalization constants
// ---------------------------------------------------------------------------
__constant__ float c_mean[CIN] = {
    -3.7189561e-06f, 0.000286194f, 0.0020740835f, 6.5275993f, -0.0052857199f,
    10.554636f, 0.057773598f, 13.915789f, 0.060970016f, 16.840271f,
    0.0570364f, 19.415283f, 0.044104282f, 21.721455f, 0.11490919f,
    23.64683f, 0.099816084f, 25.365578f, 0.01769533f, 26.861437f,
    0.054662503f, 28.197876f, -0.0024771576f, 29.295244f, 0.039666731f,
    30.319246f, 0.0088442909f, 31.160933f, -0.026727753f, 31.874565f};
__constant__ float c_var[CIN] = {
    3.3091978e-06f, 0.00016750646f, 0.80988622f, 85135.219f, 1.5621265f,
    222580.2f, 8.812871f, 386912.78f, 10.180468f, 566622.44f,
    9.8600769f, 753158.06f, 7.8372045f, 942701.62f, 30.926426f,
    1117233.0f, 25.045353f, 1285543.9f, 6.3646226f, 1441639.1f,
    12.326629f, 1588653.4f, 6.9686499f, 1714707.9f, 10.755516f,
    1836677.8f, 8.416419f, 1940088.8f, 10.344138f, 2029969.6f};

// IDFT-8 reconstruction: g[o] = sum_j cM[o][j] * comp[j],
// comps = (Re0, Re4, Re1, Im1, Re2, Im2, Re3, Im3). Verified on delta/shift.
#define S2C 0.17677669529663689f   // 0.25 * sqrt(1/2)
__constant__ float cM[8][8] = {
    {0.125f,  0.125f,  0.25f,  0.f,    0.25f,  0.f,    0.25f,  0.f  },
    {0.125f, -0.125f,  S2C,   -S2C,    0.f,   -0.25f, -S2C,   -S2C },
    {0.125f,  0.125f,  0.f,   -0.25f, -0.25f,  0.f,    0.f,    0.25f},
    {0.125f, -0.125f, -S2C,   -S2C,    0.f,    0.25f,  S2C,   -S2C },
    {0.125f,  0.125f, -0.25f,  0.f,    0.25f,  0.f,   -0.25f,  0.f  },
    {0.125f, -0.125f, -S2C,    S2C,    0.f,   -0.25f,  S2C,    S2C },
    {0.125f,  0.125f,  0.f,    0.25f, -0.25f,  0.f,    0.f,   -0.25f},
    {0.125f, -0.125f,  S2C,    S2C,    0.f,    0.25f, -S2C,    S2C }};

__device__ __forceinline__ float elu1(float x) { return x > 0.0f ? x : expm1f(x); }
__device__ __forceinline__ float elu_fast(float x) {
    float e = __expf(fminf(x, 0.0f)) - 1.0f;
    return x > 0.0f ? x : e;
}

// Forward rFFT8: x[8] -> comps (Re0,Re4,Re1,Im1,Re2,Im2,Re3,Im3)
__device__ __forceinline__ void dft8(const float* x, float* o) {
    float u04 = x[0] - x[4], e26 = x[2] - x[6];
    float p = x[1] - x[3] - x[5] + x[7];
    float q = x[1] + x[3] - x[5] - x[7];
    o[0] = x[0] + x[1] + x[2] + x[3] + x[4] + x[5] + x[6] + x[7];
    o[1] = x[0] - x[1] + x[2] - x[3] + x[4] - x[5] + x[6] - x[7];
    o[2] = u04 + SQH * p;
    o[3] = -(SQH * q + e26);
    o[4] = x[0] - x[2] + x[4] - x[6];
    o[5] = -(x[1] - x[3] + x[5] - x[7]);
    o[6] = u04 - SQH * p;
    o[7] = -SQH * q + e26;
}

// Split a float4 into hi/lo bf16x4 via packed cvt + bit-shift reconstruction.
__device__ __forceinline__ void bsplit4(const float4 v, uint2& hi, uint2& lo) {
    union { __nv_bfloat162 b; uint32_t u; } p0, p1, q0, q1;
    p0.b = __floats2bfloat162_rn(v.x, v.y);
    p1.b = __floats2bfloat162_rn(v.z, v.w);
    float fx = __uint_as_float(p0.u << 16);
    float fy = __uint_as_float(p0.u & 0xffff0000u);
    float fz = __uint_as_float(p1.u << 16);
    float fw = __uint_as_float(p1.u & 0xffff0000u);
    q0.b = __floats2bfloat162_rn(v.x - fx, v.y - fy);
    q1.b = __floats2bfloat162_rn(v.z - fz, v.w - fw);
    hi = make_uint2(p0.u, p1.u);
    lo = make_uint2(q0.u, q1.u);
}
__device__ __forceinline__ void bsplit8(const float4 va, const float4 vb,
                                        uint4& hi, uint4& lo) {
    uint2 h0, l0, h1, l1;
    bsplit4(va, h0, l0);
    bsplit4(vb, h1, l1);
    hi = make_uint4(h0.x, h0.y, h1.x, h1.y);
    lo = make_uint4(l0.x, l0.y, l1.x, l1.y);
}

// ---------------------------------------------------------------------------
// 1) Input normalization -> padded [BV, 32]
// ---------------------------------------------------------------------------
__global__ void norm_kernel(const float* __restrict__ sig, float* __restrict__ x0) {
    int i = blockIdx.x * blockDim.x + threadIdx.x;
    if (i < BV * 32) {
        int c = i & 31, bv = i >> 5;
        x0[i] = (c < CIN) ? (sig[bv * CIN + c] - c_mean[c]) * rsqrtf(c_var[c]) : 0.0f;
    }
}

// ---------------------------------------------------------------------------
// 2+3) Fused producer in frequency domain (unchanged from R16-passing).
// ---------------------------------------------------------------------------
__global__ void __launch_bounds__(128) fused_pre(
    const float* __restrict__ x, int Cp, int c8log, int lda, int kq,
    const int* __restrict__ bc_idx, const float* __restrict__ bc_w,
    __nv_bfloat16* __restrict__ Ah, __nv_bfloat16* __restrict__ Al,
    const float* __restrict__ Kw, int Tlog, int T, int isL0,
    __nv_bfloat16* __restrict__ Wh, __nv_bfloat16* __restrict__ Wl)
{
    const int tid = threadIdx.x;
    if (blockIdx.x < BV) {
        // ---------------- interp + DFT (A-side) ----------------
        __shared__ int   sidx[RA * 3];
        __shared__ float sw[RA * 3];
        const int bv = blockIdx.x;
        if (tid < RA * 3) {
            sidx[tid] = bc_idx[bv * RA * 3 + tid];
            sw[tid]   = bc_w[bv * RA * 3 + tid];
        }
        __syncthreads();
        const int C8 = 1 << c8log;
        const int items = NR << c8log;       // 5 * Cp/8
        if (tid >= items) return;
        const int c8 = tid & (C8 - 1);
        const int r  = tid >> c8log;
        const long xbase = (long)(bv >> 11) << 11;

        float X[8][8];
#pragma unroll
        for (int a = 0; a < 8; a++) {
            int ra = r * 8 + a;
            int i0 = sidx[ra * 3], i1 = sidx[ra * 3 + 1], i2 = sidx[ra * 3 + 2];
            float w0 = sw[ra * 3], w1 = sw[ra * 3 + 1], w2 = sw[ra * 3 + 2];
            const float4* r0 = (const float4*)(x + (xbase + i0) * Cp) + 2 * c8;
            const float4* r1 = (const float4*)(x + (xbase + i1) * Cp) + 2 * c8;
            const float4* r2 = (const float4*)(x + (xbase + i2) * Cp) + 2 * c8;
            float4 a0 = r0[0], a1 = r0[1];
            float4 b0 = r1[0], b1 = r1[1];
            float4 d0 = r2[0], d1 = r2[1];
            X[a][0] = w0 * a0.x + w1 * b0.x + w2 * d0.x;
            X[a][1] = w0 * a0.y + w1 * b0.y + w2 * d0.y;
            X[a][2] = w0 * a0.z + w1 * b0.z + w2 * d0.z;
            X[a][3] = w0 * a0.w + w1 * b0.w + w2 * d0.w;
            X[a][4] = w0 * a1.x + w1 * b1.x + w2 * d1.x;
            X[a][5] = w0 * a1.y + w1 * b1.y + w2 * d1.y;
            X[a][6] = w0 * a1.z + w1 * b1.z + w2 * d1.z;
            X[a][7] = w0 * a1.w + w1 * b1.w + w2 * d1.w;
        }
#pragma unroll
        for (int j = 0; j < 8; j++) {
            float xx[8], oo[8];
#pragma unroll
            for (int a = 0; a < 8; a++) xx[a] = X[a][j];
            dft8(xx, oo);
#pragma unroll
            for (int a = 0; a < 8; a++) X[a][j] = oo[a];
        }
        const long base = (long)bv * lda + r * Cp + c8 * 8;
#pragma unroll
        for (int seg = 0; seg < 8; seg++) {
            float4 va = make_float4(X[seg][0], X[seg][1], X[seg][2], X[seg][3]);
            float4 vb = make_float4(X[seg][4], X[seg][5], X[seg][6], X[seg][7]);
            uint4 hi, lo;
            bsplit8(va, vb, hi, lo);
            long off = base + (long)seg * kq;
            *(uint4*)(Ah + off) = hi;
            *(uint4*)(Al + off) = lo;
        }
    } else {
        // ---------------- W-side DFT + pack ----------------
        const int t = blockIdx.x - BV;     // [0, T)
        if (isL0) {
            // scalar path: real C=30, padded Cp=32
            for (int u = tid; u < NR * 32; u += 128) {
                int r = u >> 5, c = u & 31;
                float xx[8], oo[8];
#pragma unroll
                for (int a = 0; a < 8; a++)
                    xx[a] = (c < CIN) ? Kw[(long)(((r * 8 + a) << Tlog) + t) * CIN + c] : 0.0f;
                dft8(xx, oo);
                int base = r * 32 + c;
#define WSC(row, seg, val) do {                                             \
    float v_ = (val);                                                       \
    __nv_bfloat16 h_ = __float2bfloat16(v_);                                \
    long o_ = (long)(row) * lda + (seg) * kq + base;                        \
    Wh[o_] = h_;                                                            \
    Wl[o_] = __float2bfloat16(v_ - __bfloat162float(h_));                   \
} while (0)
                WSC(t,         0,  oo[0]);
                WSC(T + t,     1,  oo[1]);
                WSC(2*T + t,   2,  oo[2]); WSC(2*T + t, 3,  oo[3]);
                WSC(3*T + t,   2, -oo[3]); WSC(3*T + t, 3,  oo[2]);
                WSC(4*T + t,   4,  oo[4]); WSC(4*T + t, 5,  oo[5]);
                WSC(5*T + t,   4, -oo[5]); WSC(5*T + t, 5,  oo[4]);
                WSC(6*T + t,   6,  oo[6]); WSC(6*T + t, 7,  oo[7]);
                WSC(7*T + t,   6, -oo[7]); WSC(7*T + t, 7,  oo[6]);
#undef WSC
            }
        } else {
            const int C8 = 1 << c8log;
            const int items = NR << c8log;
            if (tid >= items) return;
            const int c8 = tid & (C8 - 1);
            const int r  = tid >> c8log;
            float X[8][8];
#pragma unroll
            for (int a = 0; a < 8; a++) {
                const float4* src = (const float4*)(Kw + (long)(((r * 8 + a) << Tlog) + t) * Cp) + 2 * c8;
                float4 v0 = src[0], v1 = src[1];
                X[a][0] = v0.x; X[a][1] = v0.y; X[a][2] = v0.z; X[a][3] = v0.w;
                X[a][4] = v1.x; X[a][5] = v1.y; X[a][6] = v1.z; X[a][7] = v1.w;
            }
#pragma unroll
            for (int j = 0; j < 8; j++) {
                float xx[8], oo[8];
#pragma unroll
                for (int a = 0; a < 8; a++) xx[a] = X[a][j];
                dft8(xx, oo);
#pragma unroll
                for (int a = 0; a < 8; a++) X[a][j] = oo[a];
            }
            const long cbase = r * Cp + c8 * 8;
#define WSEG(row, seg, sgn, comp) do {                                       \
    float4 va_ = make_float4(sgn X[comp][0], sgn X[comp][1],                 \
                             sgn X[comp][2], sgn X[comp][3]);                \
    float4 vb_ = make_float4(sgn X[comp][4], sgn X[comp][5],                 \
                             sgn X[comp][6], sgn X[comp][7]);                \
    uint4 hi_, lo_;                                                          \
    bsplit8(va_, vb_, hi_, lo_);                                             \
    long o_ = (long)(row) * lda + (long)(seg) * kq + cbase;                  \
    *(uint4*)(Wh + o_) = hi_;                                                \
    *(uint4*)(Wl + o_) = lo_;                                                \
} while (0)
            WSEG(t,        0, +, 0);
            WSEG(T + t,    1, +, 1);
            WSEG(2*T + t,  2, +, 2); WSEG(2*T + t, 3, +, 3);
            WSEG(3*T + t,  2, -, 3); WSEG(3*T + t, 3, +, 2);
            WSEG(4*T + t,  4, +, 4); WSEG(4*T + t, 5, +, 5);
            WSEG(5*T + t,  4, -, 5); WSEG(5*T + t, 5, +, 4);
            WSEG(6*T + t,  6, +, 6); WSEG(6*T + t, 7, +, 7);
            WSEG(7*T + t,  6, -, 7); WSEG(7*T + t, 7, +, 6);
#undef WSEG
        }
    }
}

// ---------------------------------------------------------------------------
// 4) GEMM (bf16 mma.sync, fp32 accum, 3-pass compensated), banded K.
//    MMA issue reordered for RAW distance 4 (bitwise-identical accumulation
//    order per accumulator: h -> al -> bl).
// ---------------------------------------------------------------------------
#define MAT_BYTES 8192
#define STAGE_BYTES (4 * MAT_BYTES)
#define GEMM_SMEM (3 * STAGE_BYTES)

__device__ __forceinline__ uint32_t swz(int row, int ch) {
    return (uint32_t)(row * 64 + ((ch ^ ((row >> 1) & 3)) << 4));
}

#define LOAD_STAGE(stg_off, kk) do {                                          \
    const long k0_ = (long)(kk) << 5;                                         \
    _Pragma("unroll")                                                         \
    for (int it = 0; it < 8; it++) {                                          \
        int mat = it >> 1;                                                    \
        int row = lr + (it & 1) * 64;                                         \
        long grow = (mat < 2 ? m0 : n0) + row;                                \
        const __nv_bfloat16* g = gbase[mat] + grow * ldk + k0_ + lch * 8;     \
        uint32_t dst = sb + (stg_off) + mat * MAT_BYTES + swz(row, lch);      \
        CP_ASYNC_CG(dst, g);                                                  \
    }                                                                         \
    CP_COMMIT();                                                              \
} while (0)

__global__ void __launch_bounds__(256, 2) gemm_mma(
    const __nv_bfloat16* __restrict__ Ah, const __nv_bfloat16* __restrict__ Al,
    const __nv_bfloat16* __restrict__ Wh, const __nv_bfloat16* __restrict__ Wl,
    float* __restrict__ Cout, int N, int ldk, int kq, int ulog)
{
    extern __shared__ char smem[];
    const uint32_t sb = smem_u32(smem);
    const int tid = threadIdx.x, lane = tid & 31, wid = tid >> 5;
    const int wm = (wid & 3) * 32;
    const int wn = (wid >> 2) * 64;
    const long m0 = (long)blockIdx.y * 128;
    const long n0 = (long)blockIdx.x * 128;

    // K band for this n-tile
    const int b = blockIdx.x >> ulog;
    const int kofft[8] = {0, 1, 2, 2, 4, 4, 6, 6};
    const int koff = kofft[b] * kq;
    const int klen = (b < 2) ? kq : 2 * kq;
    const int j0 = koff >> 5;
    const int j1 = j0 + (klen >> 5);

    const int lr  = (tid >> 2) & 63;
    const int lch = tid & 3;
    const __nv_bfloat16* gbase[4] = {Ah, Al, Wh, Wl};

    float acc[2][8][4];
#pragma unroll
    for (int i = 0; i < 2; i++)
#pragma unroll
        for (int j = 0; j < 8; j++)
#pragma unroll
            for (int q = 0; q < 4; q++) acc[i][j][q] = 0.0f;

    const int a_row = wm + ((lane >> 3) & 1) * 8 + (lane & 7);
    const int a_chs = lane >> 4;
    const int b_row = wn + ((lane >> 4) & 1) * 8 + (lane & 7);
    const int b_chs = (lane >> 3) & 1;

    LOAD_STAGE(0, j0);
    LOAD_STAGE(STAGE_BYTES, j0 + 1);

    uint32_t sc_off = 0;
    uint32_t sl_off = 2 * STAGE_BYTES;

    for (int j = j0; j < j1; j++) {
        if (j == j1 - 1) { CP_WAIT(0); } else { CP_WAIT(1); }
        __syncthreads();
        if (j + 2 < j1) {
            LOAD_STAGE(sl_off, j + 2);
            sl_off += STAGE_BYTES;
            if (sl_off == 3 * STAGE_BYTES) sl_off = 0;
        }

        const uint32_t base = sb + sc_off;
        sc_off += STAGE_BYTES;
        if (sc_off == 3 * STAGE_BYTES) sc_off = 0;
#pragma unroll
        for (int kg = 0; kg < 2; kg++) {
            uint32_t ah[2][4], al[2][4];
#pragma unroll
            for (int mg = 0; mg < 2; mg++) {
                int row = a_row + mg * 16;
                int ch = 2 * kg + a_chs;
                uint32_t addr = base + swz(row, ch);
                LDSM_X4(ah[mg][0], ah[mg][1], ah[mg][2], ah[mg][3], addr);
                LDSM_X4(al[mg][0], al[mg][1], al[mg][2], al[mg][3], addr + MAT_BYTES);
            }
#pragma unroll
            for (int p = 0; p < 4; p++) {
                int row = b_row + p * 16;
                int ch = 2 * kg + b_chs;
                uint32_t baddr = base + 2 * MAT_BYTES + swz(row, ch);
                uint32_t bh0, bh1, bh2, bh3, bl0, bl1, bl2, bl3;
                LDSM_X4(bh0, bh1, bh2, bh3, baddr);
                LDSM_X4(bl0, bl1, bl2, bl3, baddr + MAT_BYTES);
                // Reordered: pass-major issue, RAW distance 4 per accumulator.
                // Per-acc order remains h -> al -> bl (bitwise identical).
                MMA_BF16(acc[0][2 * p],     ah[0][0], ah[0][1], ah[0][2], ah[0][3], bh0, bh1);
                MMA_BF16(acc[1][2 * p],     ah[1][0], ah[1][1], ah[1][2], ah[1][3], bh0, bh1);
                MMA_BF16(acc[0][2 * p + 1], ah[0][0], ah[0][1], ah[0][2], ah[0][3], bh2, bh3);
                MMA_BF16(acc[1][2 * p + 1], ah[1][0], ah[1][1], ah[1][2], ah[1][3], bh2, bh3);
                MMA_BF16(acc[0][2 * p],     al[0][0], al[0][1], al[0][2], al[0][3], bh0, bh1);
                MMA_BF16(acc[1][2 * p],     al[1][0], al[1][1], al[1][2], al[1][3], bh0, bh1);
                MMA_BF16(acc[0][2 * p + 1], al[0][0], al[0][1], al[0][2], al[0][3], bh2, bh3);
                MMA_BF16(acc[1][2 * p + 1], al[1][0], al[1][1], al[1][2], al[1][3], bh2, bh3);
                MMA_BF16(acc[0][2 * p],     ah[0][0], ah[0][1], ah[0][2], ah[0][3], bl0, bl1);
                MMA_BF16(acc[1][2 * p],     ah[1][0], ah[1][1], ah[1][2], ah[1][3], bl0, bl1);
                MMA_BF16(acc[0][2 * p + 1], ah[0][0], ah[0][1], ah[0][2], ah[0][3], bl2, bl3);
                MMA_BF16(acc[1][2 * p + 1], ah[1][0], ah[1][1], ah[1][2], ah[1][3], bl2, bl3);
            }
        }
    }

    const int erow = lane >> 2;
    const int ecol = 2 * (lane & 3);
#pragma unroll
    for (int mg = 0; mg < 2; mg++) {
#pragma unroll
        for (int g = 0; g < 8; g++) {
            long row = m0 + wm + mg * 16 + erow;
            long col = n0 + wn + g * 8 + ecol;
            float2 v0 = make_float2(acc[mg][g][0], acc[mg][g][1]);
            float2 v1 = make_float2(acc[mg][g][2], acc[mg][g][3]);
            *(float2*)(Cout + row * N + col) = v0;
            *(float2*)(Cout + (row + 8) * N + col) = v1;
        }
    }
}

// ---------------------------------------------------------------------------
// 5) Epilogue: IDFT-8 reconstruct rotations + bias + ELU + AMP + BN.
// ---------------------------------------------------------------------------
__global__ void __launch_bounds__(256) amp_warp(
    const float* __restrict__ G, int T,
    const float* __restrict__ bias, const float* __restrict__ gamma,
    const float* __restrict__ beta, float* __restrict__ xnext)
{
    const int gw   = (blockIdx.x * blockDim.x + threadIdx.x) >> 5;  // vertex
    const int lane = threadIdx.x & 31;
    if (gw >= BV) return;
    const int C4T = T >> 2;
    const int nj  = C4T >> 5;
    const float4* base4 = (const float4*)(G + (long)gw * NA * T);
    const float4* b4    = (const float4*)bias;

    float4 vals[2][8];
    for (int jj = 0; jj < nj; jj++) {
        int c4 = lane + jj * 32;
#pragma unroll
        for (int k = 0; k < 8; k++)
            vals[jj][k] = base4[k * C4T + c4];
    }

    int besto = 0; float bestn = -1.0f;
#pragma unroll
    for (int o = 0; o < NA; o++) {
        float s = 0.0f;
        for (int jj = 0; jj < nj; jj++) {
            int c4 = lane + jj * 32;
            float4 v = make_float4(0.f, 0.f, 0.f, 0.f);
#pragma unroll
            for (int k = 0; k < 8; k++) {
                float m = cM[o][k];
                v.x += m * vals[jj][k].x;
                v.y += m * vals[jj][k].y;
                v.z += m * vals[jj][k].z;
                v.w += m * vals[jj][k].w;
            }
            float4 bb = b4[c4];
            float e0 = elu_fast(v.x + bb.x), e1 = elu_fast(v.y + bb.y);
            float e2 = elu_fast(v.z + bb.z), e3 = elu_fast(v.w + bb.w);
            s += e0 * e0 + e1 * e1 + e2 * e2 + e3 * e3;
        }
        s += __shfl_xor_sync(0xffffffffu, s, 16);
        s += __shfl_xor_sync(0xffffffffu, s, 8);
        s += __shfl_xor_sync(0xffffffffu, s, 4);
        s += __shfl_xor_sync(0xffffffffu, s, 2);
        s += __shfl_xor_sync(0xffffffffu, s, 1);
        if (s > bestn) { bestn = s; besto = o; }
    }
    const float scale = rsqrtf(1.0f + 1e-3f);
    const float4* g4  = (const float4*)gamma;
    const float4* be4 = (const float4*)beta;
    float4* out4 = (float4*)(xnext + (long)gw * T);
    for (int jj = 0; jj < nj; jj++) {
        int c4 = lane + jj * 32;
        float4 v = make_float4(0.f, 0.f, 0.f, 0.f);
#pragma unroll
        for (int k = 0; k < 8; k++) {
            float m = cM[besto][k];
            v.x += m * vals[jj][k].x;
            v.y += m * vals[jj][k].y;
            v.z += m * vals[jj][k].z;
            v.w += m * vals[jj][k].w;
        }
        float4 bb = b4[c4], gg = g4[c4], ee = be4[c4];
        float4 r;
        r.x = gg.x * elu_fast(v.x + bb.x) * scale + ee.x;
        r.y = gg.y * elu_fast(v.y + bb.y) * scale + ee.y;
        r.z = gg.z * elu_fast(v.z + bb.z) * scale + ee.z;
        r.w = gg.w * elu_fast(v.w + bb.w) * scale + ee.w;
        out4[c4] = r;
    }
}

// ---------------------------------------------------------------------------
// 6) Global max pool partials (float4)
// ---------------------------------------------------------------------------
__global__ void gmax_v4(const float* __restrict__ x, float* __restrict__ part) {
    int b = blockIdx.x, ch = blockIdx.y, c4 = threadIdx.x;   // 64 threads
    const float4* x4 = (const float4*)x + (long)(b * NV + ch * 128) * 64;
    float4 m = make_float4(-3.4e38f, -3.4e38f, -3.4e38f, -3.4e38f);
    for (int v = 0; v < 128; v++) {
        float4 val = x4[(long)v * 64 + c4];
        m.x = fmaxf(m.x, val.x); m.y = fmaxf(m.y, val.y);
        m.z = fmaxf(m.z, val.z); m.w = fmaxf(m.w, val.w);
    }
    ((float4*)part)[(b * 16 + ch) * 64 + c4] = m;
}

// ---------------------------------------------------------------------------
// 7) MLP head
// ---------------------------------------------------------------------------
__global__ void mlp_kernel(const float* __restrict__ part,
                           const float* __restrict__ w1, const float* __restrict__ c1,
                           const float* __restrict__ w2, const float* __restrict__ c2,
                           const float* __restrict__ w3, const float* __restrict__ c3,
                           float* __restrict__ out) {
    int b = blockIdx.x, tid = threadIdx.x;  // 512 threads
    __shared__ float h0[256], h1[512], h2[256];
    if (tid < 256) {
        float m = -3.4e38f;
        for (int ch = 0; ch < 16; ch++)
            m = fmaxf(m, part[(b * 16 + ch) * 256 + tid]);
        h0[tid] = m;
    }
    __syncthreads();
    {
        float acc = c1[tid];
        for (int k = 0; k < 256; k++) acc += h0[k] * w1[k * 512 + tid];
        h1[tid] = elu1(acc);
    }
    __syncthreads();
    if (tid < 256) {
        float acc = c2[tid];
        for (int k = 0; k < 512; k++) acc += h1[k] * w2[k * 256 + tid];
        h2[tid] = elu1(acc);
    }
    __syncthreads();
    if (tid < 40) {
        float acc = c3[tid];
        for (int k = 0; k < 256; k++) acc += h2[k] * w3[k * 40 + tid];
        out[b * 40 + tid] = acc;
    }
}

// ---------------------------------------------------------------------------
// Launch
// ---------------------------------------------------------------------------
extern "C" void kernel_launch(void* const* d_in, const int* in_sizes, int n_in,
                              void* d_out, int out_size) {
    const float* signal = (const float*)d_in[0];
    const int*   bc_idx = (const int*)  d_in[1];
    const float* bc_w   = (const float*)d_in[2];
    const float* Kw[3]  = {(const float*)d_in[3],  (const float*)d_in[7],  (const float*)d_in[11]};
    const float* Bw[3]  = {(const float*)d_in[4],  (const float*)d_in[8],  (const float*)d_in[12]};
    const float* Gw[3]  = {(const float*)d_in[5],  (const float*)d_in[9],  (const float*)d_in[13]};
    const float* Ew[3]  = {(const float*)d_in[6],  (const float*)d_in[10], (const float*)d_in[14]};
    const float* w1 = (const float*)d_in[15]; const float* c1 = (const float*)d_in[16];
    const float* w2 = (const float*)d_in[17]; const float* c2 = (const float*)d_in[18];
    const float* w3 = (const float*)d_in[19]; const float* c3 = (const float*)d_in[20];
    float* out = (float*)d_out;

    float *xA, *xB, *Gbuf, *Part;
    __nv_bfloat16 *Ah, *Al, *Wh, *Wl;
    cudaGetSymbolAddress((void**)&xA,   g_xA);
    cudaGetSymbolAddress((void**)&xB,   g_xB);
    cudaGetSymbolAddress((void**)&Ah,   g_Ah);
    cudaGetSymbolAddress((void**)&Al,   g_Al);
    cudaGetSymbolAddress((void**)&Wh,   g_Wh);
    cudaGetSymbolAddress((void**)&Wl,   g_Wl);
    cudaGetSymbolAddress((void**)&Gbuf, g_G);
    cudaGetSymbolAddress((void**)&Part, g_part);

    cudaFuncSetAttribute(gemm_mma, cudaFuncAttributeMaxDynamicSharedMemorySize, GEMM_SMEM);

    norm_kernel<<<(BV * 32 + 255) / 256, 256>>>(signal, xA);

    const int Cp[3]    = {32, 128, 128};
    const int c8log[3] = {2, 4, 4};
    const int Ts[3]    = {128, 128, 256};
    const int Tlog[3]  = {7, 7, 8};
    const int ulog3[3] = {0, 0, 1};
    float* ins[3]  = {xA, xB, xA};
    float* outs[3] = {xB, xA, xB};

    for (int l = 0; l < 3; l++) {
        int T = Ts[l];
        int kq = 5 * Cp[l];          // 160 / 640 / 640
        int lda = 8 * kq;            // 1280 / 5120 / 5120
        int N = NA * T;

        fused_pre<<<BV + T, 128>>>(ins[l], Cp[l], c8log[l], lda, kq, bc_idx, bc_w,
                                   Ah, Al, Kw[l], Tlog[l], T, l == 0 ? 1 : 0, Wh, Wl);

        dim3 grid(N / 128, BV / 128);
        gemm_mma<<<grid, 256, GEMM_SMEM>>>(Ah, Al, Wh, Wl, Gbuf, N, lda, kq, ulog3[l]);

        amp_warp<<<BV / 8, 256>>>(Gbuf, T, Bw[l], Gw[l], Ew[l], outs[l]);
    }

    gmax_v4<<<dim3(BATCH, 16), 64>>>(xB, Part);
    mlp_kernel<<<BATCH, 512>>>(Part, w1, c1, w2, c2, w3, c3, out);
}